// round 14
// baseline (speedup 1.0000x reference)
#include <cuda_runtime.h>
#include <cuda_fp16.h>
#include <mma.h>
#include <math.h>
#include <stdint.h>

using namespace nvcuda;

#define N_NODES 100000
#define N_EDGES 800000
#define DIM 128
#define TWO_N (2 * N_NODES)
#define TWO_E (2 * N_EDGES)
#define NCHUNK ((TWO_N + 1023) / 1024)   // 196

// ---------------- scratch (no cudaMalloc allowed) ----------------
__device__ __half g_xw[TWO_N * DIM];     // GEMM output (fp16) / aggregation input
__device__ __half g_h [TWO_N * DIM];     // hidden layer (fp16, sout pre-folded)
__device__ int    g_deg_out[TWO_N];
__device__ int    g_deg_in [TWO_N];
__device__ float  g_sout[TWO_N];
__device__ float  g_sin [TWO_N];
__device__ int    g_rowptr[TWO_N + 1];
__device__ int    g_cursor[TWO_N];
__device__ int    g_cols[TWO_E];
__device__ int    g_partials[NCHUNK];
__device__ int    g_pprefix [NCHUNK];
__device__ double g_sum  [2 * DIM];
__device__ double g_sumsq[2 * DIM];
__device__ float  g_mean[2 * DIM];
__device__ float  g_istd[2 * DIM];

// ---------------- build kernels ----------------
__global__ void zero_kernel() {
    int i = blockIdx.x * blockDim.x + threadIdx.x;
    if (i < TWO_N) { g_deg_out[i] = 0; g_deg_in[i] = 0; }
    if (i < 2 * DIM) { g_sum[i] = 0.0; g_sumsq[i] = 0.0; }
}

// out-degrees only (critical path for gemm1)
__global__ void degree_out_kernel(const int* __restrict__ src1, const int* __restrict__ src2) {
    int i = blockIdx.x * blockDim.x + threadIdx.x;
    if (i < TWO_E) {
        int s;
        if (i < N_EDGES) s = src1[i];
        else             s = src2[i - N_EDGES] + N_NODES;
        atomicAdd(&g_deg_out[s], 1);
    }
}

__global__ void sout_kernel() {
    int i = blockIdx.x * blockDim.x + threadIdx.x;
    if (i < TWO_N) {
        int dout = g_deg_out[i]; if (dout < 1) dout = 1;
        g_sout[i] = rsqrtf((float)dout);
    }
}

// in-degrees only (CSR branch, overlapped with gemm1)
__global__ void degree_in_kernel(const int* __restrict__ dst1, const int* __restrict__ dst2) {
    int i = blockIdx.x * blockDim.x + threadIdx.x;
    if (i < TWO_E) {
        int d;
        if (i < N_EDGES) d = dst1[i];
        else             d = dst2[i - N_EDGES] + N_NODES;
        atomicAdd(&g_deg_in[d], 1);
    }
}

__device__ __forceinline__ int block_incl_scan256(int v) {
    int lane = threadIdx.x & 31, w = threadIdx.x >> 5;
    #pragma unroll
    for (int off = 1; off < 32; off <<= 1) {
        int t = __shfl_up_sync(0xffffffffu, v, off);
        if (lane >= off) v += t;
    }
    __shared__ int ws[8];
    if (lane == 31) ws[w] = v;
    __syncthreads();
    if (w == 0 && lane < 8) {
        int x = ws[lane];
        #pragma unroll
        for (int off = 1; off < 8; off <<= 1) {
            int t = __shfl_up_sync(0xffu, x, off);
            if (lane >= off) x += t;
        }
        ws[lane] = x;
    }
    __syncthreads();
    if (w > 0) v += ws[w - 1];
    return v;
}

// partial sums of deg_in + compute sin
__global__ void scan_partial_kernel() {
    int base = blockIdx.x * 1024 + threadIdx.x * 4;
    int s = 0;
    #pragma unroll
    for (int j = 0; j < 4; j++) {
        int i = base + j;
        if (i < TWO_N) {
            int din = g_deg_in[i];
            s += din;
            if (din < 1) din = 1;
            g_sin[i] = rsqrtf((float)din);
        }
    }
    __shared__ int red[256];
    red[threadIdx.x] = s; __syncthreads();
    #pragma unroll
    for (int off = 128; off > 0; off >>= 1) {
        if (threadIdx.x < off) red[threadIdx.x] += red[threadIdx.x + off];
        __syncthreads();
    }
    if (threadIdx.x == 0) g_partials[blockIdx.x] = red[0];
}

__global__ void scan_mid_kernel() {
    int t = threadIdx.x;
    int v = (t < NCHUNK) ? g_partials[t] : 0;
    int incl = block_incl_scan256(v);
    if (t < NCHUNK) g_pprefix[t] = incl - v;
    if (t == 0) g_rowptr[TWO_N] = TWO_E;
}

__global__ void scan_final_kernel() {
    int base = blockIdx.x * 1024 + threadIdx.x * 4;
    int d[4]; int s = 0;
    #pragma unroll
    for (int j = 0; j < 4; j++) { int i = base + j; d[j] = (i < TWO_N) ? g_deg_in[i] : 0; s += d[j]; }
    int incl = block_incl_scan256(s);
    int excl = incl - s + g_pprefix[blockIdx.x];
    #pragma unroll
    for (int j = 0; j < 4; j++) {
        int i = base + j;
        if (i < TWO_N) { g_rowptr[i] = excl; g_cursor[i] = excl; excl += d[j]; }
    }
}

__global__ void scatter_kernel(const int* __restrict__ src1, const int* __restrict__ dst1,
                               const int* __restrict__ src2, const int* __restrict__ dst2) {
    int i = blockIdx.x * blockDim.x + threadIdx.x;
    if (i < TWO_E) {
        int s, d;
        if (i < N_EDGES) { s = src1[i];                     d = dst1[i]; }
        else             { s = src2[i - N_EDGES] + N_NODES; d = dst2[i - N_EDGES] + N_NODES; }
        int p = atomicAdd(&g_cursor[d], 1);
        g_cols[p] = s;
    }
}

// ============ wmma GEMMs (per-graph: row range [row_base, row_base+N_NODES)) ============
#define LDH 136
#define G_NTILES ((N_NODES + 127) / 128)         // 782 tiles per graph
#define GEMM_CTAS 148                            // full chip (staggered schedule)

// --- layer 1: fp32 input, scale by sout, fp16 hi/lo 3-term split ---
#define F32_WHI 0
#define F32_WLO (F32_WHI + 128 * LDH * 2)
#define F32_AHI (F32_WLO + 128 * LDH * 2)
#define F32_ALO (F32_AHI + 128 * LDH * 2)
#define GEMM_F32_SMEM (F32_ALO + 128 * LDH * 2)  // 139264

__global__ void __launch_bounds__(256, 1) gemm_f32_kernel(
    const float* __restrict__ X,       // this graph's features
    const float* __restrict__ W, __half* __restrict__ Yh,
    int row_base)
{
    extern __shared__ __align__(256) char smem[];
    __half* Whi = (__half*)(smem + F32_WHI);
    __half* Wlo = (__half*)(smem + F32_WLO);
    __half* Ahi = (__half*)(smem + F32_AHI);
    __half* Alo = (__half*)(smem + F32_ALO);
    float*  Cout = (float*)(smem + F32_AHI);      // reuse A region after MMA

    int tid = threadIdx.x;
    int warp = tid >> 5;
    int lane = tid & 31;
    int row_end = row_base + N_NODES;

    for (int idx = tid; idx < DIM * DIM; idx += 256) {
        int k = idx >> 7, n = idx & 127;
        float w = W[idx];
        __half hi = __float2half_rn(w);
        __half lo = __float2half_rn(w - __half2float(hi));
        Whi[k * LDH + n] = hi;
        Wlo[k * LDH + n] = lo;
    }
    __syncthreads();

    int r  = tid >> 1;
    int kh = (tid & 1) * 64;

    for (int tile = blockIdx.x; tile < G_NTILES; tile += gridDim.x) {
        int row0 = row_base + tile * 128;
        __syncthreads();

        {
            int grow = row0 + r;
            if (grow < row_end) {
                const float* Xp = X + (size_t)(grow - row_base) * DIM;
                float s = g_sout[grow];
                #pragma unroll
                for (int j = 0; j < 16; j++) {
                    int c = kh + j * 4;
                    float4 xv = *(const float4*)&Xp[c];
                    xv.x *= s; xv.y *= s; xv.z *= s; xv.w *= s;
                    __half h0 = __float2half_rn(xv.x);
                    __half h1 = __float2half_rn(xv.y);
                    __half h2 = __float2half_rn(xv.z);
                    __half h3 = __float2half_rn(xv.w);
                    __half2 hp0 = __halves2half2(h0, h1);
                    __half2 hp1 = __halves2half2(h2, h3);
                    __half2 lp0 = __halves2half2(
                        __float2half_rn(xv.x - __half2float(h0)),
                        __float2half_rn(xv.y - __half2float(h1)));
                    __half2 lp1 = __halves2half2(
                        __float2half_rn(xv.z - __half2float(h2)),
                        __float2half_rn(xv.w - __half2float(h3)));
                    uint2 hv, lv;
                    hv.x = *(uint32_t*)&hp0; hv.y = *(uint32_t*)&hp1;
                    lv.x = *(uint32_t*)&lp0; lv.y = *(uint32_t*)&lp1;
                    *(uint2*)&Ahi[r * LDH + c] = hv;
                    *(uint2*)&Alo[r * LDH + c] = lv;
                }
            } else {
                #pragma unroll
                for (int j = 0; j < 16; j++) {
                    int c = kh + j * 4;
                    *(uint2*)&Ahi[r * LDH + c] = make_uint2(0u, 0u);
                    *(uint2*)&Alo[r * LDH + c] = make_uint2(0u, 0u);
                }
            }
        }
        __syncthreads();

        wmma::fragment<wmma::accumulator, 16, 16, 16, float> acc[8];
        #pragma unroll
        for (int n = 0; n < 8; n++) wmma::fill_fragment(acc[n], 0.0f);

        #pragma unroll
        for (int kk = 0; kk < 8; kk++) {
            wmma::fragment<wmma::matrix_a, 16, 16, 16, __half, wmma::row_major> ahi, alo;
            wmma::load_matrix_sync(ahi, &Ahi[(warp * 16) * LDH + kk * 16], LDH);
            wmma::load_matrix_sync(alo, &Alo[(warp * 16) * LDH + kk * 16], LDH);
            #pragma unroll
            for (int n = 0; n < 8; n++) {
                wmma::fragment<wmma::matrix_b, 16, 16, 16, __half, wmma::row_major> bhi, blo;
                wmma::load_matrix_sync(bhi, &Whi[(kk * 16) * LDH + n * 16], LDH);
                wmma::load_matrix_sync(blo, &Wlo[(kk * 16) * LDH + n * 16], LDH);
                wmma::mma_sync(acc[n], ahi, bhi, acc[n]);
                wmma::mma_sync(acc[n], ahi, blo, acc[n]);
                wmma::mma_sync(acc[n], alo, bhi, acc[n]);
            }
        }
        __syncthreads();

        #pragma unroll
        for (int n = 0; n < 8; n++)
            wmma::store_matrix_sync(&Cout[(warp * 16) * 128 + n * 16], acc[n], 128,
                                    wmma::mem_row_major);
        __syncwarp();

        #pragma unroll
        for (int rr = 0; rr < 16; rr++) {
            int grow = row0 + warp * 16 + rr;
            if (grow < row_end) {
                float4 v = *(float4*)&Cout[(warp * 16 + rr) * 128 + lane * 4];
                __half2 a = __floats2half2_rn(v.x, v.y);
                __half2 b = __floats2half2_rn(v.z, v.w);
                uint2 o; o.x = *(uint32_t*)&a; o.y = *(uint32_t*)&b;
                *(uint2*)&Yh[(size_t)grow * DIM + lane * 4] = o;
            }
        }
    }
}

// --- layer 2: fp16 input (sout pre-folded, exact), 2-term split on W only ---
#define F16_WHI 0
#define F16_WLO (F16_WHI + 128 * LDH * 2)
#define F16_A   (F16_WLO + 128 * LDH * 2)
#define F16_C   (F16_A   + 128 * LDH * 2)        // separate fp32 C staging
#define GEMM_F16_SMEM (F16_C + 128 * 128 * 4)    // 169984

__global__ void __launch_bounds__(256, 1) gemm_f16_kernel(
    const __half* __restrict__ Xh,     // global hidden buffer (full TWO_N rows)
    const float* __restrict__ W, __half* __restrict__ Yh,
    int row_base)
{
    extern __shared__ __align__(256) char smem[];
    __half* Whi = (__half*)(smem + F16_WHI);
    __half* Wlo = (__half*)(smem + F16_WLO);
    __half* As  = (__half*)(smem + F16_A);
    float*  Cout = (float*)(smem + F16_C);

    int tid = threadIdx.x;
    int warp = tid >> 5;
    int lane = tid & 31;
    int row_end = row_base + N_NODES;

    for (int idx = tid; idx < DIM * DIM; idx += 256) {
        int k = idx >> 7, n = idx & 127;
        float w = W[idx];
        __half hi = __float2half_rn(w);
        __half lo = __float2half_rn(w - __half2float(hi));
        Whi[k * LDH + n] = hi;
        Wlo[k * LDH + n] = lo;
    }
    __syncthreads();

    int r  = tid >> 1;
    int kh = (tid & 1) * 64;

    for (int tile = blockIdx.x; tile < G_NTILES; tile += gridDim.x) {
        int row0 = row_base + tile * 128;
        __syncthreads();

        {
            int grow = row0 + r;
            if (grow < row_end) {
                const uint4* src = (const uint4*)&Xh[(size_t)grow * DIM + kh];
                uint4* dst = (uint4*)&As[r * LDH + kh];
                #pragma unroll
                for (int j = 0; j < 8; j++) dst[j] = src[j];
            } else {
                uint4* dst = (uint4*)&As[r * LDH + kh];
                #pragma unroll
                for (int j = 0; j < 8; j++) dst[j] = make_uint4(0u, 0u, 0u, 0u);
            }
        }
        __syncthreads();

        wmma::fragment<wmma::accumulator, 16, 16, 16, float> acc[8];
        #pragma unroll
        for (int n = 0; n < 8; n++) wmma::fill_fragment(acc[n], 0.0f);

        #pragma unroll
        for (int kk = 0; kk < 8; kk++) {
            wmma::fragment<wmma::matrix_a, 16, 16, 16, __half, wmma::row_major> a;
            wmma::load_matrix_sync(a, &As[(warp * 16) * LDH + kk * 16], LDH);
            #pragma unroll
            for (int n = 0; n < 8; n++) {
                wmma::fragment<wmma::matrix_b, 16, 16, 16, __half, wmma::row_major> bhi, blo;
                wmma::load_matrix_sync(bhi, &Whi[(kk * 16) * LDH + n * 16], LDH);
                wmma::load_matrix_sync(blo, &Wlo[(kk * 16) * LDH + n * 16], LDH);
                wmma::mma_sync(acc[n], a, bhi, acc[n]);
                wmma::mma_sync(acc[n], a, blo, acc[n]);
            }
        }

        #pragma unroll
        for (int n = 0; n < 8; n++)
            wmma::store_matrix_sync(&Cout[(warp * 16) * 128 + n * 16], acc[n], 128,
                                    wmma::mem_row_major);
        __syncwarp();

        #pragma unroll
        for (int rr = 0; rr < 16; rr++) {
            int grow = row0 + warp * 16 + rr;
            if (grow < row_end) {
                float4 v = *(float4*)&Cout[(warp * 16 + rr) * 128 + lane * 4];
                __half2 a = __floats2half2_rn(v.x, v.y);
                __half2 b = __floats2half2_rn(v.z, v.w);
                uint2 o; o.x = *(uint32_t*)&a; o.y = *(uint32_t*)&b;
                *(uint2*)&Yh[(size_t)grow * DIM + lane * 4] = o;
            }
        }
    }
}

// ---------------- shared agg body: fp16 gather, warp per node (MLP x2) ----------------
__device__ __forceinline__ float4 agg_gather(const __half* __restrict__ Xw,
                                             int node, int lane)
{
    int r0 = g_rowptr[node];
    int r1 = g_rowptr[node + 1];
    float4 a0 = make_float4(0.f, 0.f, 0.f, 0.f);
    float4 a1 = make_float4(0.f, 0.f, 0.f, 0.f);
    int e = r0;
    for (; e + 1 < r1; e += 2) {
        int c0 = g_cols[e], c1 = g_cols[e + 1];
        uint2 u0 = *(const uint2*)&Xw[(size_t)c0 * DIM + lane * 4];
        uint2 u1 = *(const uint2*)&Xw[(size_t)c1 * DIM + lane * 4];
        float2 p0 = __half22float2(*(__half2*)&u0.x);
        float2 q0 = __half22float2(*(__half2*)&u0.y);
        float2 p1 = __half22float2(*(__half2*)&u1.x);
        float2 q1 = __half22float2(*(__half2*)&u1.y);
        a0.x += p0.x; a0.y += p0.y; a0.z += q0.x; a0.w += q0.y;
        a1.x += p1.x; a1.y += p1.y; a1.z += q1.x; a1.w += q1.y;
    }
    if (e < r1) {
        int c0 = g_cols[e];
        uint2 u0 = *(const uint2*)&Xw[(size_t)c0 * DIM + lane * 4];
        float2 p0 = __half22float2(*(__half2*)&u0.x);
        float2 q0 = __half22float2(*(__half2*)&u0.y);
        a0.x += p0.x; a0.y += p0.y; a0.z += q0.x; a0.w += q0.y;
    }
    a0.x += a1.x; a0.y += a1.y; a0.z += a1.z; a0.w += a1.w;
    return a0;
}

// agg1 (per graph): h' = relu(agg*sin + b) * sout, fp16 out; one node per warp
__global__ void agg1_kernel(const __half* __restrict__ Xw,
                            const float* __restrict__ bias,
                            __half* __restrict__ outh, int node_base)
{
    int n = (blockIdx.x * blockDim.x + threadIdx.x) >> 5;
    int lane = threadIdx.x & 31;
    if (n >= N_NODES) return;
    int node = node_base + n;
    float4 a = agg_gather(Xw, node, lane);
    float s = g_sin[node];
    float so = g_sout[node];
    float4 b = *(const float4*)&bias[lane * 4];
    float4 o;
    o.x = fmaxf(a.x * s + b.x, 0.f) * so;
    o.y = fmaxf(a.y * s + b.y, 0.f) * so;
    o.z = fmaxf(a.z * s + b.z, 0.f) * so;
    o.w = fmaxf(a.w * s + b.w, 0.f) * so;
    __half2 p = __floats2half2_rn(o.x, o.y);
    __half2 q = __floats2half2_rn(o.z, o.w);
    uint2 u; u.x = *(uint32_t*)&p; u.y = *(uint32_t*)&q;
    *(uint2*)&outh[(size_t)node * DIM + lane * 4] = u;
}

// agg2 (per graph): out = agg*sin + b (fp32), fused register column stats
#define AGG2_BPG 296

__global__ void __launch_bounds__(256) agg2_kernel(const __half* __restrict__ Xw,
                            const float* __restrict__ bias,
                            float* __restrict__ out, int graph)
{
    __shared__ float ssum[8][128];
    __shared__ float ssq [8][128];

    int tid = threadIdx.x;
    int wip = tid >> 5;
    int lane = tid & 31;
    int wg = blockIdx.x * 8 + wip;
    const int WSTRIDE = AGG2_BPG * 8;
    int nbase = graph * N_NODES;

    float4 b = *(const float4*)&bias[lane * 4];
    float4 rsum = make_float4(0.f, 0.f, 0.f, 0.f);
    float4 rsq  = make_float4(0.f, 0.f, 0.f, 0.f);

    for (int n = wg; n < N_NODES; n += WSTRIDE) {
        int node = nbase + n;
        float4 a = agg_gather(Xw, node, lane);
        float s = g_sin[node];
        float4 o;
        o.x = a.x * s + b.x; o.y = a.y * s + b.y;
        o.z = a.z * s + b.z; o.w = a.w * s + b.w;
        *(float4*)&out[(size_t)node * DIM + lane * 4] = o;
        rsum.x += o.x; rsum.y += o.y; rsum.z += o.z; rsum.w += o.w;
        rsq.x += o.x * o.x; rsq.y += o.y * o.y;
        rsq.z += o.z * o.z; rsq.w += o.w * o.w;
    }

    *(float4*)&ssum[wip][lane * 4] = rsum;
    *(float4*)&ssq [wip][lane * 4] = rsq;
    __syncthreads();

    if (tid < 128) {
        float ts = 0.f, tq = 0.f;
        #pragma unroll
        for (int w = 0; w < 8; w++) { ts += ssum[w][tid]; tq += ssq[w][tid]; }
        atomicAdd(&g_sum  [graph * DIM + tid], (double)ts);
        atomicAdd(&g_sumsq[graph * DIM + tid], (double)tq);
    }
}

// ---------------- per-graph stats finalize + z-score ----------------
__global__ void finalize_stats_kernel(int graph) {
    int c = threadIdx.x;
    if (c < DIM) {
        int m = graph * DIM + c;
        double mean = g_sum[m] / (double)N_NODES;
        double var  = (g_sumsq[m] - mean * mean * (double)N_NODES) / (double)(N_NODES - 1);
        g_mean[m] = (float)mean;
        g_istd[m] = (float)(1.0 / sqrt(var));
    }
}

__global__ void norm_kernel(float* __restrict__ h, int graph) {
    int i = blockIdx.x * blockDim.x + threadIdx.x;
    const int total = N_NODES * DIM / 4;
    if (i < total) {
        float4* p = (float4*)h + (size_t)graph * total + i;
        float4 v = *p;
        int c = (i * 4) & 127;
        int m = graph * DIM + c;
        v.x = (v.x - g_mean[m + 0]) * g_istd[m + 0];
        v.y = (v.y - g_mean[m + 1]) * g_istd[m + 1];
        v.z = (v.z - g_mean[m + 2]) * g_istd[m + 2];
        v.w = (v.w - g_mean[m + 3]) * g_istd[m + 3];
        *p = v;
    }
}

// ---------------- launch ----------------
extern "C" void kernel_launch(void* const* d_in, const int* in_sizes, int n_in,
                              void* d_out, int out_size)
{
    const float* feat1 = (const float*)d_in[0];
    const float* feat2 = (const float*)d_in[1];
    const float* W1    = (const float*)d_in[2];
    const float* b1    = (const float*)d_in[3];
    const float* W2    = (const float*)d_in[4];
    const float* b2    = (const float*)d_in[5];
    const int*   src1  = (const int*)d_in[6];
    const int*   dst1  = (const int*)d_in[7];
    const int*   src2  = (const int*)d_in[8];
    const int*   dst2  = (const int*)d_in[9];
    float* out = (float*)d_out;

    static cudaStream_t s2 = nullptr, s3 = nullptr;
    static cudaEvent_t ev_zero = nullptr, ev_sout = nullptr,
                       ev_csr = nullptr, ev_g1 = nullptr, ev_stag = nullptr;
    if (!s2) {
        cudaStreamCreateWithFlags(&s2, cudaStreamNonBlocking);
        cudaStreamCreateWithFlags(&s3, cudaStreamNonBlocking);
        cudaEventCreateWithFlags(&ev_zero, cudaEventDisableTiming);
        cudaEventCreateWithFlags(&ev_sout, cudaEventDisableTiming);
        cudaEventCreateWithFlags(&ev_csr,  cudaEventDisableTiming);
        cudaEventCreateWithFlags(&ev_g1,   cudaEventDisableTiming);
        cudaEventCreateWithFlags(&ev_stag, cudaEventDisableTiming);
        cudaFuncSetAttribute(gemm_f32_kernel,
                             cudaFuncAttributeMaxDynamicSharedMemorySize, GEMM_F32_SMEM);
        cudaFuncSetAttribute(gemm_f16_kernel,
                             cudaFuncAttributeMaxDynamicSharedMemorySize, GEMM_F16_SMEM);
    }

    __half* p_xw = nullptr; __half* p_h = nullptr;
    cudaGetSymbolAddress((void**)&p_xw, g_xw);
    cudaGetSymbolAddress((void**)&p_h,  g_h);

    const int NB_2N  = (TWO_N + 255) / 256;
    const int NB_2E  = (TWO_E + 255) / 256;
    const int NB_AGG1 = (N_NODES * 32 + 255) / 256;      // 12500 blocks per graph
    const int NB_NORM = (N_NODES * DIM / 4 + 255) / 256; // per graph

    // ---- stream 0: minimal critical path to GEMM-1 ----
    zero_kernel<<<NB_2N, 256>>>();
    cudaEventRecord(ev_zero, 0);
    degree_out_kernel<<<NB_2E, 256>>>(src1, src2);
    sout_kernel<<<NB_2N, 256>>>();
    cudaEventRecord(ev_sout, 0);

    // ---- s2: in-degree + CSR chain (hidden under GEMM-1) ----
    cudaStreamWaitEvent(s2, ev_zero, 0);
    degree_in_kernel<<<NB_2E, 256, 0, s2>>>(dst1, dst2);
    scan_partial_kernel<<<NCHUNK, 256, 0, s2>>>();   // sin + partials
    scan_mid_kernel<<<1, 256, 0, s2>>>();
    scan_final_kernel<<<NCHUNK, 256, 0, s2>>>();
    scatter_kernel<<<NB_2E, 256, 0, s2>>>(src1, dst1, src2, dst2);
    cudaEventRecord(ev_csr, s2);

    // ---- graph 0 pipeline on stream 0 (full-chip GEMMs) ----
    gemm_f32_kernel<<<GEMM_CTAS, 256, GEMM_F32_SMEM>>>(feat1, W1, p_xw, 0);
    cudaEventRecord(ev_stag, 0);                 // stagger point: G1(g0) done
    cudaStreamWaitEvent(0, ev_csr, 0);
    agg1_kernel<<<NB_AGG1, 256>>>(p_xw, b1, p_h, 0);
    gemm_f16_kernel<<<GEMM_CTAS, 256, GEMM_F16_SMEM>>>(p_h, W2, p_xw, 0);
    agg2_kernel<<<AGG2_BPG, 256>>>(p_xw, b2, out, 0);
    finalize_stats_kernel<<<1, 128>>>(0);
    norm_kernel<<<NB_NORM, 256>>>(out, 0);

    // ---- graph 1 pipeline on s3, staggered one phase behind ----
    cudaStreamWaitEvent(s3, ev_sout, 0);
    cudaStreamWaitEvent(s3, ev_stag, 0);         // start G1(g1) alongside A1(g0)
    gemm_f32_kernel<<<GEMM_CTAS, 256, GEMM_F32_SMEM, s3>>>(feat2, W1, p_xw, N_NODES);
    cudaStreamWaitEvent(s3, ev_csr, 0);
    agg1_kernel<<<NB_AGG1, 256, 0, s3>>>(p_xw, b1, p_h, N_NODES);
    gemm_f16_kernel<<<GEMM_CTAS, 256, GEMM_F16_SMEM, s3>>>(p_h, W2, p_xw, N_NODES);
    agg2_kernel<<<AGG2_BPG, 256, 0, s3>>>(p_xw, b2, out, 1);
    finalize_stats_kernel<<<1, 128, 0, s3>>>(1);
    norm_kernel<<<NB_NORM, 256, 0, s3>>>(out, 1);
    cudaEventRecord(ev_g1, s3);

    // join so the captured graph's stream-0 tail covers both branches
    cudaStreamWaitEvent(0, ev_g1, 0);
}

// round 15
// speedup vs baseline: 1.0731x; 1.0731x over previous
#include <cuda_runtime.h>
#include <cuda_fp16.h>
#include <mma.h>
#include <math.h>
#include <stdint.h>

using namespace nvcuda;

#define N_NODES 100000
#define N_EDGES 800000
#define DIM 128
#define TWO_N (2 * N_NODES)
#define TWO_E (2 * N_EDGES)
#define NCHUNK ((TWO_N + 1023) / 1024)   // 196

// ---------------- scratch (no cudaMalloc allowed) ----------------
__device__ __half g_xw[TWO_N * DIM];
__device__ __half g_h [TWO_N * DIM];
__device__ int    g_deg_out[TWO_N];
__device__ int    g_deg_in [TWO_N];
__device__ float  g_sout[TWO_N];
__device__ float  g_sin [TWO_N];
__device__ int    g_rowptr[TWO_N + 1];
__device__ int    g_cursor[TWO_N];
__device__ int    g_cols[TWO_E];
__device__ int    g_partials[NCHUNK];
__device__ int    g_pprefix [NCHUNK];
__device__ double g_sum  [2 * DIM];
__device__ double g_sumsq[2 * DIM];
__device__ float  g_mean[2 * DIM];
__device__ float  g_istd[2 * DIM];

// ---------------- build kernels ----------------
__global__ void zero_kernel() {
    int i = blockIdx.x * blockDim.x + threadIdx.x;
    if (i < TWO_N) { g_deg_out[i] = 0; g_deg_in[i] = 0; }
    if (i < 2 * DIM) { g_sum[i] = 0.0; g_sumsq[i] = 0.0; }
}

__global__ void degree_out_kernel(const int* __restrict__ src1, const int* __restrict__ src2) {
    int i = blockIdx.x * blockDim.x + threadIdx.x;
    if (i < TWO_E) {
        int s;
        if (i < N_EDGES) s = src1[i];
        else             s = src2[i - N_EDGES] + N_NODES;
        atomicAdd(&g_deg_out[s], 1);
    }
}

__global__ void sout_kernel() {
    int i = blockIdx.x * blockDim.x + threadIdx.x;
    if (i < TWO_N) {
        int dout = g_deg_out[i]; if (dout < 1) dout = 1;
        g_sout[i] = rsqrtf((float)dout);
    }
}

__global__ void degree_in_kernel(const int* __restrict__ dst1, const int* __restrict__ dst2) {
    int i = blockIdx.x * blockDim.x + threadIdx.x;
    if (i < TWO_E) {
        int d;
        if (i < N_EDGES) d = dst1[i];
        else             d = dst2[i - N_EDGES] + N_NODES;
        atomicAdd(&g_deg_in[d], 1);
    }
}

__device__ __forceinline__ int block_incl_scan256(int v) {
    int lane = threadIdx.x & 31, w = threadIdx.x >> 5;
    #pragma unroll
    for (int off = 1; off < 32; off <<= 1) {
        int t = __shfl_up_sync(0xffffffffu, v, off);
        if (lane >= off) v += t;
    }
    __shared__ int ws[8];
    if (lane == 31) ws[w] = v;
    __syncthreads();
    if (w == 0 && lane < 8) {
        int x = ws[lane];
        #pragma unroll
        for (int off = 1; off < 8; off <<= 1) {
            int t = __shfl_up_sync(0xffu, x, off);
            if (lane >= off) x += t;
        }
        ws[lane] = x;
    }
    __syncthreads();
    if (w > 0) v += ws[w - 1];
    return v;
}

__global__ void scan_partial_kernel() {
    int base = blockIdx.x * 1024 + threadIdx.x * 4;
    int s = 0;
    #pragma unroll
    for (int j = 0; j < 4; j++) {
        int i = base + j;
        if (i < TWO_N) {
            int din = g_deg_in[i];
            s += din;
            if (din < 1) din = 1;
            g_sin[i] = rsqrtf((float)din);
        }
    }
    __shared__ int red[256];
    red[threadIdx.x] = s; __syncthreads();
    #pragma unroll
    for (int off = 128; off > 0; off >>= 1) {
        if (threadIdx.x < off) red[threadIdx.x] += red[threadIdx.x + off];
        __syncthreads();
    }
    if (threadIdx.x == 0) g_partials[blockIdx.x] = red[0];
}

__global__ void scan_mid_kernel() {
    int t = threadIdx.x;
    int v = (t < NCHUNK) ? g_partials[t] : 0;
    int incl = block_incl_scan256(v);
    if (t < NCHUNK) g_pprefix[t] = incl - v;
    if (t == 0) g_rowptr[TWO_N] = TWO_E;
}

__global__ void scan_final_kernel() {
    int base = blockIdx.x * 1024 + threadIdx.x * 4;
    int d[4]; int s = 0;
    #pragma unroll
    for (int j = 0; j < 4; j++) { int i = base + j; d[j] = (i < TWO_N) ? g_deg_in[i] : 0; s += d[j]; }
    int incl = block_incl_scan256(s);
    int excl = incl - s + g_pprefix[blockIdx.x];
    #pragma unroll
    for (int j = 0; j < 4; j++) {
        int i = base + j;
        if (i < TWO_N) { g_rowptr[i] = excl; g_cursor[i] = excl; excl += d[j]; }
    }
}

__global__ void scatter_kernel(const int* __restrict__ src1, const int* __restrict__ dst1,
                               const int* __restrict__ src2, const int* __restrict__ dst2) {
    int i = blockIdx.x * blockDim.x + threadIdx.x;
    if (i < TWO_E) {
        int s, d;
        if (i < N_EDGES) { s = src1[i];                     d = dst1[i]; }
        else             { s = src2[i - N_EDGES] + N_NODES; d = dst2[i - N_EDGES] + N_NODES; }
        int p = atomicAdd(&g_cursor[d], 1);
        g_cols[p] = s;
    }
}

// ============ wmma GEMMs ============
#define LDH 136
#define G_NTILES ((N_NODES + 127) / 128)         // 782 tiles per graph
#define GEMM_CTAS 74
#define HALF_TILES 391
#define HALF_NODES (HALF_TILES * 128)            // 50048

// --- layer 1: fp32 input, scale by sout, fp16 hi/lo 3-term split ---
#define F32_WHI 0
#define F32_WLO (F32_WHI + 128 * LDH * 2)
#define F32_AHI (F32_WLO + 128 * LDH * 2)
#define F32_ALO (F32_AHI + 128 * LDH * 2)
#define GEMM_F32_SMEM (F32_ALO + 128 * LDH * 2)  // 139264

__global__ void __launch_bounds__(256, 1) gemm_f32_kernel(
    const float* __restrict__ X,
    const float* __restrict__ W, __half* __restrict__ Yh,
    int row_base)
{
    extern __shared__ __align__(256) char smem[];
    __half* Whi = (__half*)(smem + F32_WHI);
    __half* Wlo = (__half*)(smem + F32_WLO);
    __half* Ahi = (__half*)(smem + F32_AHI);
    __half* Alo = (__half*)(smem + F32_ALO);
    float*  Cout = (float*)(smem + F32_AHI);

    int tid = threadIdx.x;
    int warp = tid >> 5;
    int lane = tid & 31;
    int row_end = row_base + N_NODES;

    for (int idx = tid; idx < DIM * DIM; idx += 256) {
        int k = idx >> 7, n = idx & 127;
        float w = W[idx];
        __half hi = __float2half_rn(w);
        __half lo = __float2half_rn(w - __half2float(hi));
        Whi[k * LDH + n] = hi;
        Wlo[k * LDH + n] = lo;
    }
    __syncthreads();

    int r  = tid >> 1;
    int kh = (tid & 1) * 64;

    for (int tile = blockIdx.x; tile < G_NTILES; tile += gridDim.x) {
        int row0 = row_base + tile * 128;
        __syncthreads();

        {
            int grow = row0 + r;
            if (grow < row_end) {
                const float* Xp = X + (size_t)(grow - row_base) * DIM;
                float s = g_sout[grow];
                #pragma unroll
                for (int j = 0; j < 16; j++) {
                    int c = kh + j * 4;
                    float4 xv = *(const float4*)&Xp[c];
                    xv.x *= s; xv.y *= s; xv.z *= s; xv.w *= s;
                    __half h0 = __float2half_rn(xv.x);
                    __half h1 = __float2half_rn(xv.y);
                    __half h2 = __float2half_rn(xv.z);
                    __half h3 = __float2half_rn(xv.w);
                    __half2 hp0 = __halves2half2(h0, h1);
                    __half2 hp1 = __halves2half2(h2, h3);
                    __half2 lp0 = __halves2half2(
                        __float2half_rn(xv.x - __half2float(h0)),
                        __float2half_rn(xv.y - __half2float(h1)));
                    __half2 lp1 = __halves2half2(
                        __float2half_rn(xv.z - __half2float(h2)),
                        __float2half_rn(xv.w - __half2float(h3)));
                    uint2 hv, lv;
                    hv.x = *(uint32_t*)&hp0; hv.y = *(uint32_t*)&hp1;
                    lv.x = *(uint32_t*)&lp0; lv.y = *(uint32_t*)&lp1;
                    *(uint2*)&Ahi[r * LDH + c] = hv;
                    *(uint2*)&Alo[r * LDH + c] = lv;
                }
            } else {
                #pragma unroll
                for (int j = 0; j < 16; j++) {
                    int c = kh + j * 4;
                    *(uint2*)&Ahi[r * LDH + c] = make_uint2(0u, 0u);
                    *(uint2*)&Alo[r * LDH + c] = make_uint2(0u, 0u);
                }
            }
        }
        __syncthreads();

        wmma::fragment<wmma::accumulator, 16, 16, 16, float> acc[8];
        #pragma unroll
        for (int n = 0; n < 8; n++) wmma::fill_fragment(acc[n], 0.0f);

        #pragma unroll
        for (int kk = 0; kk < 8; kk++) {
            wmma::fragment<wmma::matrix_a, 16, 16, 16, __half, wmma::row_major> ahi, alo;
            wmma::load_matrix_sync(ahi, &Ahi[(warp * 16) * LDH + kk * 16], LDH);
            wmma::load_matrix_sync(alo, &Alo[(warp * 16) * LDH + kk * 16], LDH);
            #pragma unroll
            for (int n = 0; n < 8; n++) {
                wmma::fragment<wmma::matrix_b, 16, 16, 16, __half, wmma::row_major> bhi, blo;
                wmma::load_matrix_sync(bhi, &Whi[(kk * 16) * LDH + n * 16], LDH);
                wmma::load_matrix_sync(blo, &Wlo[(kk * 16) * LDH + n * 16], LDH);
                wmma::mma_sync(acc[n], ahi, bhi, acc[n]);
                wmma::mma_sync(acc[n], ahi, blo, acc[n]);
                wmma::mma_sync(acc[n], alo, bhi, acc[n]);
            }
        }
        __syncthreads();

        #pragma unroll
        for (int n = 0; n < 8; n++)
            wmma::store_matrix_sync(&Cout[(warp * 16) * 128 + n * 16], acc[n], 128,
                                    wmma::mem_row_major);
        __syncwarp();

        #pragma unroll
        for (int rr = 0; rr < 16; rr++) {
            int grow = row0 + warp * 16 + rr;
            if (grow < row_end) {
                float4 v = *(float4*)&Cout[(warp * 16 + rr) * 128 + lane * 4];
                __half2 a = __floats2half2_rn(v.x, v.y);
                __half2 b = __floats2half2_rn(v.z, v.w);
                uint2 o; o.x = *(uint32_t*)&a; o.y = *(uint32_t*)&b;
                *(uint2*)&Yh[(size_t)grow * DIM + lane * 4] = o;
            }
        }
    }
}

// --- layer 2: fp16 input, 2-term split; processes [tile_start, tile_start+ntiles) ---
#define F16_WHI 0
#define F16_WLO (F16_WHI + 128 * LDH * 2)
#define F16_A   (F16_WLO + 128 * LDH * 2)
#define F16_C   (F16_A   + 128 * LDH * 2)
#define GEMM_F16_SMEM (F16_C + 128 * 128 * 4)    // 169984

__global__ void __launch_bounds__(256, 1) gemm_f16_kernel(
    const __half* __restrict__ Xh,
    const float* __restrict__ W, __half* __restrict__ Yh,
    int row_base, int tile_start, int ntiles)
{
    extern __shared__ __align__(256) char smem[];
    __half* Whi = (__half*)(smem + F16_WHI);
    __half* Wlo = (__half*)(smem + F16_WLO);
    __half* As  = (__half*)(smem + F16_A);
    float*  Cout = (float*)(smem + F16_C);

    int tid = threadIdx.x;
    int warp = tid >> 5;
    int lane = tid & 31;
    int row_end = row_base + N_NODES;

    for (int idx = tid; idx < DIM * DIM; idx += 256) {
        int k = idx >> 7, n = idx & 127;
        float w = W[idx];
        __half hi = __float2half_rn(w);
        __half lo = __float2half_rn(w - __half2float(hi));
        Whi[k * LDH + n] = hi;
        Wlo[k * LDH + n] = lo;
    }
    __syncthreads();

    int r  = tid >> 1;
    int kh = (tid & 1) * 64;

    for (int t = blockIdx.x; t < ntiles; t += gridDim.x) {
        int row0 = row_base + (tile_start + t) * 128;
        __syncthreads();

        {
            int grow = row0 + r;
            if (grow < row_end) {
                const uint4* src = (const uint4*)&Xh[(size_t)grow * DIM + kh];
                uint4* dst = (uint4*)&As[r * LDH + kh];
                #pragma unroll
                for (int j = 0; j < 8; j++) dst[j] = src[j];
            } else {
                uint4* dst = (uint4*)&As[r * LDH + kh];
                #pragma unroll
                for (int j = 0; j < 8; j++) dst[j] = make_uint4(0u, 0u, 0u, 0u);
            }
        }
        __syncthreads();

        wmma::fragment<wmma::accumulator, 16, 16, 16, float> acc[8];
        #pragma unroll
        for (int n = 0; n < 8; n++) wmma::fill_fragment(acc[n], 0.0f);

        #pragma unroll
        for (int kk = 0; kk < 8; kk++) {
            wmma::fragment<wmma::matrix_a, 16, 16, 16, __half, wmma::row_major> a;
            wmma::load_matrix_sync(a, &As[(warp * 16) * LDH + kk * 16], LDH);
            #pragma unroll
            for (int n = 0; n < 8; n++) {
                wmma::fragment<wmma::matrix_b, 16, 16, 16, __half, wmma::row_major> bhi, blo;
                wmma::load_matrix_sync(bhi, &Whi[(kk * 16) * LDH + n * 16], LDH);
                wmma::load_matrix_sync(blo, &Wlo[(kk * 16) * LDH + n * 16], LDH);
                wmma::mma_sync(acc[n], a, bhi, acc[n]);
                wmma::mma_sync(acc[n], a, blo, acc[n]);
            }
        }

        #pragma unroll
        for (int n = 0; n < 8; n++)
            wmma::store_matrix_sync(&Cout[(warp * 16) * 128 + n * 16], acc[n], 128,
                                    wmma::mem_row_major);
        __syncwarp();

        #pragma unroll
        for (int rr = 0; rr < 16; rr++) {
            int grow = row0 + warp * 16 + rr;
            if (grow < row_end) {
                float4 v = *(float4*)&Cout[(warp * 16 + rr) * 128 + lane * 4];
                __half2 a = __floats2half2_rn(v.x, v.y);
                __half2 b = __floats2half2_rn(v.z, v.w);
                uint2 o; o.x = *(uint32_t*)&a; o.y = *(uint32_t*)&b;
                *(uint2*)&Yh[(size_t)grow * DIM + lane * 4] = o;
            }
        }
    }
}

// ---------------- shared agg body: fp16 gather, warp per node (MLP x2) ----------------
__device__ __forceinline__ float4 agg_gather(const __half* __restrict__ Xw,
                                             int node, int lane)
{
    int r0 = g_rowptr[node];
    int r1 = g_rowptr[node + 1];
    float4 a0 = make_float4(0.f, 0.f, 0.f, 0.f);
    float4 a1 = make_float4(0.f, 0.f, 0.f, 0.f);
    int e = r0;
    for (; e + 1 < r1; e += 2) {
        int c0 = g_cols[e], c1 = g_cols[e + 1];
        uint2 u0 = *(const uint2*)&Xw[(size_t)c0 * DIM + lane * 4];
        uint2 u1 = *(const uint2*)&Xw[(size_t)c1 * DIM + lane * 4];
        float2 p0 = __half22float2(*(__half2*)&u0.x);
        float2 q0 = __half22float2(*(__half2*)&u0.y);
        float2 p1 = __half22float2(*(__half2*)&u1.x);
        float2 q1 = __half22float2(*(__half2*)&u1.y);
        a0.x += p0.x; a0.y += p0.y; a0.z += q0.x; a0.w += q0.y;
        a1.x += p1.x; a1.y += p1.y; a1.z += q1.x; a1.w += q1.y;
    }
    if (e < r1) {
        int c0 = g_cols[e];
        uint2 u0 = *(const uint2*)&Xw[(size_t)c0 * DIM + lane * 4];
        float2 p0 = __half22float2(*(__half2*)&u0.x);
        float2 q0 = __half22float2(*(__half2*)&u0.y);
        a0.x += p0.x; a0.y += p0.y; a0.z += q0.x; a0.w += q0.y;
    }
    a0.x += a1.x; a0.y += a1.y; a0.z += a1.z; a0.w += a1.w;
    return a0;
}

// agg1: node range [node_start, node_start+count); one node per warp
__global__ void agg1_kernel(const __half* __restrict__ Xw,
                            const float* __restrict__ bias,
                            __half* __restrict__ outh, int node_start, int count)
{
    int n = (blockIdx.x * blockDim.x + threadIdx.x) >> 5;
    int lane = threadIdx.x & 31;
    if (n >= count) return;
    int node = node_start + n;
    float4 a = agg_gather(Xw, node, lane);
    float s = g_sin[node];
    float so = g_sout[node];
    float4 b = *(const float4*)&bias[lane * 4];
    float4 o;
    o.x = fmaxf(a.x * s + b.x, 0.f) * so;
    o.y = fmaxf(a.y * s + b.y, 0.f) * so;
    o.z = fmaxf(a.z * s + b.z, 0.f) * so;
    o.w = fmaxf(a.w * s + b.w, 0.f) * so;
    __half2 p = __floats2half2_rn(o.x, o.y);
    __half2 q = __floats2half2_rn(o.z, o.w);
    uint2 u; u.x = *(uint32_t*)&p; u.y = *(uint32_t*)&q;
    *(uint2*)&outh[(size_t)node * DIM + lane * 4] = u;
}

// agg2 (per graph): out = agg*sin + b (fp32), fused register column stats
#define AGG2_BPG 296

__global__ void __launch_bounds__(256) agg2_kernel(const __half* __restrict__ Xw,
                            const float* __restrict__ bias,
                            float* __restrict__ out, int graph)
{
    __shared__ float ssum[8][128];
    __shared__ float ssq [8][128];

    int tid = threadIdx.x;
    int wip = tid >> 5;
    int lane = tid & 31;
    int wg = blockIdx.x * 8 + wip;
    const int WSTRIDE = AGG2_BPG * 8;
    int nbase = graph * N_NODES;

    float4 b = *(const float4*)&bias[lane * 4];
    float4 rsum = make_float4(0.f, 0.f, 0.f, 0.f);
    float4 rsq  = make_float4(0.f, 0.f, 0.f, 0.f);

    for (int n = wg; n < N_NODES; n += WSTRIDE) {
        int node = nbase + n;
        float4 a = agg_gather(Xw, node, lane);
        float s = g_sin[node];
        float4 o;
        o.x = a.x * s + b.x; o.y = a.y * s + b.y;
        o.z = a.z * s + b.z; o.w = a.w * s + b.w;
        *(float4*)&out[(size_t)node * DIM + lane * 4] = o;
        rsum.x += o.x; rsum.y += o.y; rsum.z += o.z; rsum.w += o.w;
        rsq.x += o.x * o.x; rsq.y += o.y * o.y;
        rsq.z += o.z * o.z; rsq.w += o.w * o.w;
    }

    *(float4*)&ssum[wip][lane * 4] = rsum;
    *(float4*)&ssq [wip][lane * 4] = rsq;
    __syncthreads();

    if (tid < 128) {
        float ts = 0.f, tq = 0.f;
        #pragma unroll
        for (int w = 0; w < 8; w++) { ts += ssum[w][tid]; tq += ssq[w][tid]; }
        atomicAdd(&g_sum  [graph * DIM + tid], (double)ts);
        atomicAdd(&g_sumsq[graph * DIM + tid], (double)tq);
    }
}

// ---------------- per-graph stats finalize + z-score ----------------
__global__ void finalize_stats_kernel(int graph) {
    int c = threadIdx.x;
    if (c < DIM) {
        int m = graph * DIM + c;
        double mean = g_sum[m] / (double)N_NODES;
        double var  = (g_sumsq[m] - mean * mean * (double)N_NODES) / (double)(N_NODES - 1);
        g_mean[m] = (float)mean;
        g_istd[m] = (float)(1.0 / sqrt(var));
    }
}

__global__ void norm_kernel(float* __restrict__ h, int graph) {
    int i = blockIdx.x * blockDim.x + threadIdx.x;
    const int total = N_NODES * DIM / 4;
    if (i < total) {
        float4* p = (float4*)h + (size_t)graph * total + i;
        float4 v = *p;
        int c = (i * 4) & 127;
        int m = graph * DIM + c;
        v.x = (v.x - g_mean[m + 0]) * g_istd[m + 0];
        v.y = (v.y - g_mean[m + 1]) * g_istd[m + 1];
        v.z = (v.z - g_mean[m + 2]) * g_istd[m + 2];
        v.w = (v.w - g_mean[m + 3]) * g_istd[m + 3];
        *p = v;
    }
}

// ---------------- launch ----------------
extern "C" void kernel_launch(void* const* d_in, const int* in_sizes, int n_in,
                              void* d_out, int out_size)
{
    const float* feat1 = (const float*)d_in[0];
    const float* feat2 = (const float*)d_in[1];
    const float* W1    = (const float*)d_in[2];
    const float* b1    = (const float*)d_in[3];
    const float* W2    = (const float*)d_in[4];
    const float* b2    = (const float*)d_in[5];
    const int*   src1  = (const int*)d_in[6];
    const int*   dst1  = (const int*)d_in[7];
    const int*   src2  = (const int*)d_in[8];
    const int*   dst2  = (const int*)d_in[9];
    float* out = (float*)d_out;

    static cudaStream_t s2 = nullptr, s3 = nullptr, s4 = nullptr;
    static cudaEvent_t ev_zero = nullptr, ev_sout = nullptr, ev_csr = nullptr,
                       ev_end1 = nullptr,
                       ev_h0 = nullptr, ev_g0a = nullptr,      // graph 0 pipeline
                       ev_h1 = nullptr, ev_g1a = nullptr;      // graph 1 pipeline
    if (!s2) {
        cudaStreamCreateWithFlags(&s2, cudaStreamNonBlocking);
        cudaStreamCreateWithFlags(&s3, cudaStreamNonBlocking);
        cudaStreamCreateWithFlags(&s4, cudaStreamNonBlocking);
        cudaEventCreateWithFlags(&ev_zero, cudaEventDisableTiming);
        cudaEventCreateWithFlags(&ev_sout, cudaEventDisableTiming);
        cudaEventCreateWithFlags(&ev_csr,  cudaEventDisableTiming);
        cudaEventCreateWithFlags(&ev_end1, cudaEventDisableTiming);
        cudaEventCreateWithFlags(&ev_h0,   cudaEventDisableTiming);
        cudaEventCreateWithFlags(&ev_g0a,  cudaEventDisableTiming);
        cudaEventCreateWithFlags(&ev_h1,   cudaEventDisableTiming);
        cudaEventCreateWithFlags(&ev_g1a,  cudaEventDisableTiming);
        cudaFuncSetAttribute(gemm_f32_kernel,
                             cudaFuncAttributeMaxDynamicSharedMemorySize, GEMM_F32_SMEM);
        cudaFuncSetAttribute(gemm_f16_kernel,
                             cudaFuncAttributeMaxDynamicSharedMemorySize, GEMM_F16_SMEM);
    }

    __half* p_xw = nullptr; __half* p_h = nullptr;
    cudaGetSymbolAddress((void**)&p_xw, g_xw);
    cudaGetSymbolAddress((void**)&p_h,  g_h);

    const int NB_2N  = (TWO_N + 255) / 256;
    const int NB_2E  = (TWO_E + 255) / 256;
    const int NB_A1H0 = (HALF_NODES * 32 + 255) / 256;              // 6256
    const int NB_A1H1 = ((N_NODES - HALF_NODES) * 32 + 255) / 256;  // 6244
    const int NB_NORM = (N_NODES * DIM / 4 + 255) / 256;

    // ---- stream 0: minimal critical path to GEMM-1 ----
    zero_kernel<<<NB_2N, 256>>>();
    cudaEventRecord(ev_zero, 0);
    degree_out_kernel<<<NB_2E, 256>>>(src1, src2);
    sout_kernel<<<NB_2N, 256>>>();
    cudaEventRecord(ev_sout, 0);

    // ---- s2: in-degree + CSR chain (hidden under GEMM-1) ----
    cudaStreamWaitEvent(s2, ev_zero, 0);
    degree_in_kernel<<<NB_2E, 256, 0, s2>>>(dst1, dst2);
    scan_partial_kernel<<<NCHUNK, 256, 0, s2>>>();
    scan_mid_kernel<<<1, 256, 0, s2>>>();
    scan_final_kernel<<<NCHUNK, 256, 0, s2>>>();
    scatter_kernel<<<NB_2E, 256, 0, s2>>>(src1, dst1, src2, dst2);
    cudaEventRecord(ev_csr, s2);

    // ---- graph 0 pipeline: main = stream 0, helper = s2 (free after CSR) ----
    gemm_f32_kernel<<<GEMM_CTAS, 256, GEMM_F32_SMEM>>>(feat1, W1, p_xw, 0);
    cudaStreamWaitEvent(0, ev_csr, 0);
    agg1_kernel<<<NB_A1H0, 256>>>(p_xw, b1, p_h, 0, HALF_NODES);
    cudaEventRecord(ev_h0, 0);
    agg1_kernel<<<NB_A1H1, 256>>>(p_xw, b1, p_h, HALF_NODES, N_NODES - HALF_NODES);
    // helper: gemm16 half0 as soon as agg1 half0 done
    cudaStreamWaitEvent(s2, ev_h0, 0);
    gemm_f16_kernel<<<GEMM_CTAS, 256, GEMM_F16_SMEM, s2>>>(p_h, W2, p_xw, 0, 0, HALF_TILES);
    cudaEventRecord(ev_g0a, s2);
    // main: gemm16 half1 (agg1 half1 done on this stream)
    gemm_f16_kernel<<<GEMM_CTAS, 256, GEMM_F16_SMEM>>>(p_h, W2, p_xw, 0, HALF_TILES, G_NTILES - HALF_TILES);
    cudaStreamWaitEvent(0, ev_g0a, 0);
    agg2_kernel<<<AGG2_BPG, 256>>>(p_xw, b2, out, 0);
    finalize_stats_kernel<<<1, 128>>>(0);
    norm_kernel<<<NB_NORM, 256>>>(out, 0);

    // ---- graph 1 pipeline: main = s3, helper = s4 ----
    cudaStreamWaitEvent(s3, ev_sout, 0);
    gemm_f32_kernel<<<GEMM_CTAS, 256, GEMM_F32_SMEM, s3>>>(feat2, W1, p_xw, N_NODES);
    cudaStreamWaitEvent(s3, ev_csr, 0);
    agg1_kernel<<<NB_A1H0, 256, 0, s3>>>(p_xw, b1, p_h, N_NODES, HALF_NODES);
    cudaEventRecord(ev_h1, s3);
    agg1_kernel<<<NB_A1H1, 256, 0, s3>>>(p_xw, b1, p_h, N_NODES + HALF_NODES, N_NODES - HALF_NODES);
    cudaStreamWaitEvent(s4, ev_h1, 0);
    gemm_f16_kernel<<<GEMM_CTAS, 256, GEMM_F16_SMEM, s4>>>(p_h, W2, p_xw, N_NODES, 0, HALF_TILES);
    cudaEventRecord(ev_g1a, s4);
    gemm_f16_kernel<<<GEMM_CTAS, 256, GEMM_F16_SMEM, s3>>>(p_h, W2, p_xw, N_NODES, HALF_TILES, G_NTILES - HALF_TILES);
    cudaStreamWaitEvent(s3, ev_g1a, 0);
    agg2_kernel<<<AGG2_BPG, 256, 0, s3>>>(p_xw, b2, out, 1);
    finalize_stats_kernel<<<1, 128, 0, s3>>>(1);
    norm_kernel<<<NB_NORM, 256, 0, s3>>>(out, 1);
    cudaEventRecord(ev_end1, s3);

    // join
    cudaStreamWaitEvent(0, ev_end1, 0);
}

// round 16
// speedup vs baseline: 1.1135x; 1.0376x over previous
#include <cuda_runtime.h>
#include <cuda_fp16.h>
#include <mma.h>
#include <math.h>
#include <stdint.h>

using namespace nvcuda;

#define N_NODES 100000
#define N_EDGES 800000
#define DIM 128
#define TWO_N (2 * N_NODES)
#define TWO_E (2 * N_EDGES)
#define NCHUNK ((TWO_N + 1023) / 1024)   // 196

// ---------------- scratch (no cudaMalloc allowed) ----------------
__device__ __half g_xw[TWO_N * DIM];     // GEMM output (fp16) / aggregation input
__device__ __half g_h [TWO_N * DIM];     // hidden layer (fp16, sout pre-folded)
__device__ int    g_deg_out[TWO_N];
__device__ int    g_deg_in [TWO_N];
__device__ float  g_sout[TWO_N];
__device__ float  g_sin [TWO_N];
__device__ int    g_rowptr[TWO_N + 1];
__device__ int    g_cursor[TWO_N];
__device__ int    g_cols[TWO_E];
__device__ int    g_partials[NCHUNK];
__device__ int    g_pprefix [NCHUNK];
__device__ double g_sum  [2 * DIM];
__device__ double g_sumsq[2 * DIM];
__device__ float  g_mean[2 * DIM];
__device__ float  g_istd[2 * DIM];

// ---------------- build kernels ----------------
__global__ void zero_kernel() {
    int i = blockIdx.x * blockDim.x + threadIdx.x;
    if (i < TWO_N) { g_deg_out[i] = 0; g_deg_in[i] = 0; }
    if (i < 2 * DIM) { g_sum[i] = 0.0; g_sumsq[i] = 0.0; }
}

// out-degrees only (critical path for gemm1)
__global__ void degree_out_kernel(const int* __restrict__ src1, const int* __restrict__ src2) {
    int i = blockIdx.x * blockDim.x + threadIdx.x;
    if (i < TWO_E) {
        int s;
        if (i < N_EDGES) s = src1[i];
        else             s = src2[i - N_EDGES] + N_NODES;
        atomicAdd(&g_deg_out[s], 1);
    }
}

__global__ void sout_kernel() {
    int i = blockIdx.x * blockDim.x + threadIdx.x;
    if (i < TWO_N) {
        int dout = g_deg_out[i]; if (dout < 1) dout = 1;
        g_sout[i] = rsqrtf((float)dout);
    }
}

// in-degrees only (CSR branch, overlapped with gemm1)
__global__ void degree_in_kernel(const int* __restrict__ dst1, const int* __restrict__ dst2) {
    int i = blockIdx.x * blockDim.x + threadIdx.x;
    if (i < TWO_E) {
        int d;
        if (i < N_EDGES) d = dst1[i];
        else             d = dst2[i - N_EDGES] + N_NODES;
        atomicAdd(&g_deg_in[d], 1);
    }
}

__device__ __forceinline__ int block_incl_scan256(int v) {
    int lane = threadIdx.x & 31, w = threadIdx.x >> 5;
    #pragma unroll
    for (int off = 1; off < 32; off <<= 1) {
        int t = __shfl_up_sync(0xffffffffu, v, off);
        if (lane >= off) v += t;
    }
    __shared__ int ws[8];
    if (lane == 31) ws[w] = v;
    __syncthreads();
    if (w == 0 && lane < 8) {
        int x = ws[lane];
        #pragma unroll
        for (int off = 1; off < 8; off <<= 1) {
            int t = __shfl_up_sync(0xffu, x, off);
            if (lane >= off) x += t;
        }
        ws[lane] = x;
    }
    __syncthreads();
    if (w > 0) v += ws[w - 1];
    return v;
}

// partial sums of deg_in + compute sin
__global__ void scan_partial_kernel() {
    int base = blockIdx.x * 1024 + threadIdx.x * 4;
    int s = 0;
    #pragma unroll
    for (int j = 0; j < 4; j++) {
        int i = base + j;
        if (i < TWO_N) {
            int din = g_deg_in[i];
            s += din;
            if (din < 1) din = 1;
            g_sin[i] = rsqrtf((float)din);
        }
    }
    __shared__ int red[256];
    red[threadIdx.x] = s; __syncthreads();
    #pragma unroll
    for (int off = 128; off > 0; off >>= 1) {
        if (threadIdx.x < off) red[threadIdx.x] += red[threadIdx.x + off];
        __syncthreads();
    }
    if (threadIdx.x == 0) g_partials[blockIdx.x] = red[0];
}

__global__ void scan_mid_kernel() {
    int t = threadIdx.x;
    int v = (t < NCHUNK) ? g_partials[t] : 0;
    int incl = block_incl_scan256(v);
    if (t < NCHUNK) g_pprefix[t] = incl - v;
    if (t == 0) g_rowptr[TWO_N] = TWO_E;
}

__global__ void scan_final_kernel() {
    int base = blockIdx.x * 1024 + threadIdx.x * 4;
    int d[4]; int s = 0;
    #pragma unroll
    for (int j = 0; j < 4; j++) { int i = base + j; d[j] = (i < TWO_N) ? g_deg_in[i] : 0; s += d[j]; }
    int incl = block_incl_scan256(s);
    int excl = incl - s + g_pprefix[blockIdx.x];
    #pragma unroll
    for (int j = 0; j < 4; j++) {
        int i = base + j;
        if (i < TWO_N) { g_rowptr[i] = excl; g_cursor[i] = excl; excl += d[j]; }
    }
}

__global__ void scatter_kernel(const int* __restrict__ src1, const int* __restrict__ dst1,
                               const int* __restrict__ src2, const int* __restrict__ dst2) {
    int i = blockIdx.x * blockDim.x + threadIdx.x;
    if (i < TWO_E) {
        int s, d;
        if (i < N_EDGES) { s = src1[i];                     d = dst1[i]; }
        else             { s = src2[i - N_EDGES] + N_NODES; d = dst2[i - N_EDGES] + N_NODES; }
        int p = atomicAdd(&g_cursor[d], 1);
        g_cols[p] = s;
    }
}

// ============ wmma GEMMs (per-graph: row range [row_base, row_base+N_NODES)) ============
#define LDH 136
#define G_NTILES ((N_NODES + 127) / 128)         // 782 tiles per graph
#define GEMM_CTAS 74                             // half-chip: two graphs co-reside

// --- layer 1: fp32 input, scale by sout, A fp16 (2-term: A·Whi + A·Wlo) ---
#define F32_WHI 0
#define F32_WLO (F32_WHI + 128 * LDH * 2)
#define F32_A   (F32_WLO + 128 * LDH * 2)
#define F32_C   (F32_A   + 128 * LDH * 2)        // fp32 C staging
#define GEMM_F32_SMEM (F32_C + 128 * 128 * 4)    // 169984

__global__ void __launch_bounds__(256, 1) gemm_f32_kernel(
    const float* __restrict__ X,       // this graph's features
    const float* __restrict__ W, __half* __restrict__ Yh,
    int row_base)
{
    extern __shared__ __align__(256) char smem[];
    __half* Whi = (__half*)(smem + F32_WHI);
    __half* Wlo = (__half*)(smem + F32_WLO);
    __half* As  = (__half*)(smem + F32_A);
    float*  Cout = (float*)(smem + F32_C);

    int tid = threadIdx.x;
    int warp = tid >> 5;
    int lane = tid & 31;
    int row_end = row_base + N_NODES;

    for (int idx = tid; idx < DIM * DIM; idx += 256) {
        int k = idx >> 7, n = idx & 127;
        float w = W[idx];
        __half hi = __float2half_rn(w);
        __half lo = __float2half_rn(w - __half2float(hi));
        Whi[k * LDH + n] = hi;
        Wlo[k * LDH + n] = lo;
    }
    __syncthreads();

    int r  = tid >> 1;
    int kh = (tid & 1) * 64;

    for (int tile = blockIdx.x; tile < G_NTILES; tile += gridDim.x) {
        int row0 = row_base + tile * 128;
        __syncthreads();

        {
            int grow = row0 + r;
            if (grow < row_end) {
                const float* Xp = X + (size_t)(grow - row_base) * DIM;
                float s = g_sout[grow];
                #pragma unroll
                for (int j = 0; j < 16; j++) {
                    int c = kh + j * 4;
                    float4 xv = *(const float4*)&Xp[c];
                    __half2 p = __floats2half2_rn(xv.x * s, xv.y * s);
                    __half2 q = __floats2half2_rn(xv.z * s, xv.w * s);
                    uint2 u; u.x = *(uint32_t*)&p; u.y = *(uint32_t*)&q;
                    *(uint2*)&As[r * LDH + c] = u;
                }
            } else {
                #pragma unroll
                for (int j = 0; j < 16; j++) {
                    int c = kh + j * 4;
                    *(uint2*)&As[r * LDH + c] = make_uint2(0u, 0u);
                }
            }
        }
        __syncthreads();

        wmma::fragment<wmma::accumulator, 16, 16, 16, float> acc[8];
        #pragma unroll
        for (int n = 0; n < 8; n++) wmma::fill_fragment(acc[n], 0.0f);

        #pragma unroll
        for (int kk = 0; kk < 8; kk++) {
            wmma::fragment<wmma::matrix_a, 16, 16, 16, __half, wmma::row_major> a;
            wmma::load_matrix_sync(a, &As[(warp * 16) * LDH + kk * 16], LDH);
            #pragma unroll
            for (int n = 0; n < 8; n++) {
                wmma::fragment<wmma::matrix_b, 16, 16, 16, __half, wmma::row_major> bhi, blo;
                wmma::load_matrix_sync(bhi, &Whi[(kk * 16) * LDH + n * 16], LDH);
                wmma::load_matrix_sync(blo, &Wlo[(kk * 16) * LDH + n * 16], LDH);
                wmma::mma_sync(acc[n], a, bhi, acc[n]);
                wmma::mma_sync(acc[n], a, blo, acc[n]);
            }
        }

        #pragma unroll
        for (int n = 0; n < 8; n++)
            wmma::store_matrix_sync(&Cout[(warp * 16) * 128 + n * 16], acc[n], 128,
                                    wmma::mem_row_major);
        __syncwarp();

        #pragma unroll
        for (int rr = 0; rr < 16; rr++) {
            int grow = row0 + warp * 16 + rr;
            if (grow < row_end) {
                float4 v = *(float4*)&Cout[(warp * 16 + rr) * 128 + lane * 4];
                __half2 a = __floats2half2_rn(v.x, v.y);
                __half2 b = __floats2half2_rn(v.z, v.w);
                uint2 o; o.x = *(uint32_t*)&a; o.y = *(uint32_t*)&b;
                *(uint2*)&Yh[(size_t)grow * DIM + lane * 4] = o;
            }
        }
    }
}

// --- layer 2: fp16 input (sout pre-folded, exact), 2-term split on W only ---
#define F16_WHI 0
#define F16_WLO (F16_WHI + 128 * LDH * 2)
#define F16_A   (F16_WLO + 128 * LDH * 2)
#define F16_C   (F16_A   + 128 * LDH * 2)        // separate fp32 C staging
#define GEMM_F16_SMEM (F16_C + 128 * 128 * 4)    // 169984

__global__ void __launch_bounds__(256, 1) gemm_f16_kernel(
    const __half* __restrict__ Xh,     // global hidden buffer (full TWO_N rows)
    const float* __restrict__ W, __half* __restrict__ Yh,
    int row_base)
{
    extern __shared__ __align__(256) char smem[];
    __half* Whi = (__half*)(smem + F16_WHI);
    __half* Wlo = (__half*)(smem + F16_WLO);
    __half* As  = (__half*)(smem + F16_A);
    float*  Cout = (float*)(smem + F16_C);

    int tid = threadIdx.x;
    int warp = tid >> 5;
    int lane = tid & 31;
    int row_end = row_base + N_NODES;

    for (int idx = tid; idx < DIM * DIM; idx += 256) {
        int k = idx >> 7, n = idx & 127;
        float w = W[idx];
        __half hi = __float2half_rn(w);
        __half lo = __float2half_rn(w - __half2float(hi));
        Whi[k * LDH + n] = hi;
        Wlo[k * LDH + n] = lo;
    }
    __syncthreads();

    int r  = tid >> 1;
    int kh = (tid & 1) * 64;

    for (int tile = blockIdx.x; tile < G_NTILES; tile += gridDim.x) {
        int row0 = row_base + tile * 128;
        __syncthreads();

        {
            int grow = row0 + r;
            if (grow < row_end) {
                const uint4* src = (const uint4*)&Xh[(size_t)grow * DIM + kh];
                uint4* dst = (uint4*)&As[r * LDH + kh];
                #pragma unroll
                for (int j = 0; j < 8; j++) dst[j] = src[j];
            } else {
                uint4* dst = (uint4*)&As[r * LDH + kh];
                #pragma unroll
                for (int j = 0; j < 8; j++) dst[j] = make_uint4(0u, 0u, 0u, 0u);
            }
        }
        __syncthreads();

        wmma::fragment<wmma::accumulator, 16, 16, 16, float> acc[8];
        #pragma unroll
        for (int n = 0; n < 8; n++) wmma::fill_fragment(acc[n], 0.0f);

        #pragma unroll
        for (int kk = 0; kk < 8; kk++) {
            wmma::fragment<wmma::matrix_a, 16, 16, 16, __half, wmma::row_major> a;
            wmma::load_matrix_sync(a, &As[(warp * 16) * LDH + kk * 16], LDH);
            #pragma unroll
            for (int n = 0; n < 8; n++) {
                wmma::fragment<wmma::matrix_b, 16, 16, 16, __half, wmma::row_major> bhi, blo;
                wmma::load_matrix_sync(bhi, &Whi[(kk * 16) * LDH + n * 16], LDH);
                wmma::load_matrix_sync(blo, &Wlo[(kk * 16) * LDH + n * 16], LDH);
                wmma::mma_sync(acc[n], a, bhi, acc[n]);
                wmma::mma_sync(acc[n], a, blo, acc[n]);
            }
        }

        #pragma unroll
        for (int n = 0; n < 8; n++)
            wmma::store_matrix_sync(&Cout[(warp * 16) * 128 + n * 16], acc[n], 128,
                                    wmma::mem_row_major);
        __syncwarp();

        #pragma unroll
        for (int rr = 0; rr < 16; rr++) {
            int grow = row0 + warp * 16 + rr;
            if (grow < row_end) {
                float4 v = *(float4*)&Cout[(warp * 16 + rr) * 128 + lane * 4];
                __half2 a = __floats2half2_rn(v.x, v.y);
                __half2 b = __floats2half2_rn(v.z, v.w);
                uint2 o; o.x = *(uint32_t*)&a; o.y = *(uint32_t*)&b;
                *(uint2*)&Yh[(size_t)grow * DIM + lane * 4] = o;
            }
        }
    }
}

// ---------------- shared agg body: fp16 gather, warp per node (MLP x2) ----------------
__device__ __forceinline__ float4 agg_gather(const __half* __restrict__ Xw,
                                             int node, int lane)
{
    int r0 = g_rowptr[node];
    int r1 = g_rowptr[node + 1];
    float4 a0 = make_float4(0.f, 0.f, 0.f, 0.f);
    float4 a1 = make_float4(0.f, 0.f, 0.f, 0.f);
    int e = r0;
    for (; e + 1 < r1; e += 2) {
        int c0 = g_cols[e], c1 = g_cols[e + 1];
        uint2 u0 = *(const uint2*)&Xw[(size_t)c0 * DIM + lane * 4];
        uint2 u1 = *(const uint2*)&Xw[(size_t)c1 * DIM + lane * 4];
        float2 p0 = __half22float2(*(__half2*)&u0.x);
        float2 q0 = __half22float2(*(__half2*)&u0.y);
        float2 p1 = __half22float2(*(__half2*)&u1.x);
        float2 q1 = __half22float2(*(__half2*)&u1.y);
        a0.x += p0.x; a0.y += p0.y; a0.z += q0.x; a0.w += q0.y;
        a1.x += p1.x; a1.y += p1.y; a1.z += q1.x; a1.w += q1.y;
    }
    if (e < r1) {
        int c0 = g_cols[e];
        uint2 u0 = *(const uint2*)&Xw[(size_t)c0 * DIM + lane * 4];
        float2 p0 = __half22float2(*(__half2*)&u0.x);
        float2 q0 = __half22float2(*(__half2*)&u0.y);
        a0.x += p0.x; a0.y += p0.y; a0.z += q0.x; a0.w += q0.y;
    }
    a0.x += a1.x; a0.y += a1.y; a0.z += a1.z; a0.w += a1.w;
    return a0;
}

// agg1 (per graph): h' = relu(agg*sin + b) * sout, fp16 out; one node per warp
__global__ void agg1_kernel(const __half* __restrict__ Xw,
                            const float* __restrict__ bias,
                            __half* __restrict__ outh, int node_base)
{
    int n = (blockIdx.x * blockDim.x + threadIdx.x) >> 5;
    int lane = threadIdx.x & 31;
    if (n >= N_NODES) return;
    int node = node_base + n;
    float4 a = agg_gather(Xw, node, lane);
    float s = g_sin[node];
    float so = g_sout[node];
    float4 b = *(const float4*)&bias[lane * 4];
    float4 o;
    o.x = fmaxf(a.x * s + b.x, 0.f) * so;
    o.y = fmaxf(a.y * s + b.y, 0.f) * so;
    o.z = fmaxf(a.z * s + b.z, 0.f) * so;
    o.w = fmaxf(a.w * s + b.w, 0.f) * so;
    __half2 p = __floats2half2_rn(o.x, o.y);
    __half2 q = __floats2half2_rn(o.z, o.w);
    uint2 u; u.x = *(uint32_t*)&p; u.y = *(uint32_t*)&q;
    *(uint2*)&outh[(size_t)node * DIM + lane * 4] = u;
}

// agg2 (per graph): out = agg*sin + b (fp32), fused register column stats
#define AGG2_BPG 296

__global__ void __launch_bounds__(256) agg2_kernel(const __half* __restrict__ Xw,
                            const float* __restrict__ bias,
                            float* __restrict__ out, int graph)
{
    __shared__ float ssum[8][128];
    __shared__ float ssq [8][128];

    int tid = threadIdx.x;
    int wip = tid >> 5;
    int lane = tid & 31;
    int wg = blockIdx.x * 8 + wip;
    const int WSTRIDE = AGG2_BPG * 8;
    int nbase = graph * N_NODES;

    float4 b = *(const float4*)&bias[lane * 4];
    float4 rsum = make_float4(0.f, 0.f, 0.f, 0.f);
    float4 rsq  = make_float4(0.f, 0.f, 0.f, 0.f);

    for (int n = wg; n < N_NODES; n += WSTRIDE) {
        int node = nbase + n;
        float4 a = agg_gather(Xw, node, lane);
        float s = g_sin[node];
        float4 o;
        o.x = a.x * s + b.x; o.y = a.y * s + b.y;
        o.z = a.z * s + b.z; o.w = a.w * s + b.w;
        *(float4*)&out[(size_t)node * DIM + lane * 4] = o;
        rsum.x += o.x; rsum.y += o.y; rsum.z += o.z; rsum.w += o.w;
        rsq.x += o.x * o.x; rsq.y += o.y * o.y;
        rsq.z += o.z * o.z; rsq.w += o.w * o.w;
    }

    *(float4*)&ssum[wip][lane * 4] = rsum;
    *(float4*)&ssq [wip][lane * 4] = rsq;
    __syncthreads();

    if (tid < 128) {
        float ts = 0.f, tq = 0.f;
        #pragma unroll
        for (int w = 0; w < 8; w++) { ts += ssum[w][tid]; tq += ssq[w][tid]; }
        atomicAdd(&g_sum  [graph * DIM + tid], (double)ts);
        atomicAdd(&g_sumsq[graph * DIM + tid], (double)tq);
    }
}

// ---------------- per-graph stats finalize + z-score ----------------
__global__ void finalize_stats_kernel(int graph) {
    int c = threadIdx.x;
    if (c < DIM) {
        int m = graph * DIM + c;
        double mean = g_sum[m] / (double)N_NODES;
        double var  = (g_sumsq[m] - mean * mean * (double)N_NODES) / (double)(N_NODES - 1);
        g_mean[m] = (float)mean;
        g_istd[m] = (float)(1.0 / sqrt(var));
    }
}

__global__ void norm_kernel(float* __restrict__ h, int graph) {
    int i = blockIdx.x * blockDim.x + threadIdx.x;
    const int total = N_NODES * DIM / 4;
    if (i < total) {
        float4* p = (float4*)h + (size_t)graph * total + i;
        float4 v = *p;
        int c = (i * 4) & 127;
        int m = graph * DIM + c;
        v.x = (v.x - g_mean[m + 0]) * g_istd[m + 0];
        v.y = (v.y - g_mean[m + 1]) * g_istd[m + 1];
        v.z = (v.z - g_mean[m + 2]) * g_istd[m + 2];
        v.w = (v.w - g_mean[m + 3]) * g_istd[m + 3];
        *p = v;
    }
}

// ---------------- launch ----------------
extern "C" void kernel_launch(void* const* d_in, const int* in_sizes, int n_in,
                              void* d_out, int out_size)
{
    const float* feat1 = (const float*)d_in[0];
    const float* feat2 = (const float*)d_in[1];
    const float* W1    = (const float*)d_in[2];
    const float* b1    = (const float*)d_in[3];
    const float* W2    = (const float*)d_in[4];
    const float* b2    = (const float*)d_in[5];
    const int*   src1  = (const int*)d_in[6];
    const int*   dst1  = (const int*)d_in[7];
    const int*   src2  = (const int*)d_in[8];
    const int*   dst2  = (const int*)d_in[9];
    float* out = (float*)d_out;

    static cudaStream_t s2 = nullptr, s3 = nullptr;
    static cudaEvent_t ev_zero = nullptr, ev_sout = nullptr,
                       ev_csr = nullptr, ev_g1 = nullptr;
    if (!s2) {
        cudaStreamCreateWithFlags(&s2, cudaStreamNonBlocking);
        cudaStreamCreateWithFlags(&s3, cudaStreamNonBlocking);
        cudaEventCreateWithFlags(&ev_zero, cudaEventDisableTiming);
        cudaEventCreateWithFlags(&ev_sout, cudaEventDisableTiming);
        cudaEventCreateWithFlags(&ev_csr,  cudaEventDisableTiming);
        cudaEventCreateWithFlags(&ev_g1,   cudaEventDisableTiming);
        cudaFuncSetAttribute(gemm_f32_kernel,
                             cudaFuncAttributeMaxDynamicSharedMemorySize, GEMM_F32_SMEM);
        cudaFuncSetAttribute(gemm_f16_kernel,
                             cudaFuncAttributeMaxDynamicSharedMemorySize, GEMM_F16_SMEM);
    }

    __half* p_xw = nullptr; __half* p_h = nullptr;
    cudaGetSymbolAddress((void**)&p_xw, g_xw);
    cudaGetSymbolAddress((void**)&p_h,  g_h);

    const int NB_2N  = (TWO_N + 255) / 256;
    const int NB_2E  = (TWO_E + 255) / 256;
    const int NB_AGG1 = (N_NODES * 32 + 255) / 256;      // 12500 blocks per graph
    const int NB_NORM = (N_NODES * DIM / 4 + 255) / 256; // per graph

    // ---- stream 0: minimal critical path to GEMM-1 ----
    zero_kernel<<<NB_2N, 256>>>();
    cudaEventRecord(ev_zero, 0);
    degree_out_kernel<<<NB_2E, 256>>>(src1, src2);
    sout_kernel<<<NB_2N, 256>>>();
    cudaEventRecord(ev_sout, 0);

    // ---- s2: in-degree + CSR chain (hidden under GEMM-1) ----
    cudaStreamWaitEvent(s2, ev_zero, 0);
    degree_in_kernel<<<NB_2E, 256, 0, s2>>>(dst1, dst2);
    scan_partial_kernel<<<NCHUNK, 256, 0, s2>>>();   // sin + partials
    scan_mid_kernel<<<1, 256, 0, s2>>>();
    scan_final_kernel<<<NCHUNK, 256, 0, s2>>>();
    scatter_kernel<<<NB_2E, 256, 0, s2>>>(src1, dst1, src2, dst2);
    cudaEventRecord(ev_csr, s2);

    // ---- graph 0 pipeline on stream 0 ----
    gemm_f32_kernel<<<GEMM_CTAS, 256, GEMM_F32_SMEM>>>(feat1, W1, p_xw, 0);
    cudaStreamWaitEvent(0, ev_csr, 0);
    agg1_kernel<<<NB_AGG1, 256>>>(p_xw, b1, p_h, 0);
    gemm_f16_kernel<<<GEMM_CTAS, 256, GEMM_F16_SMEM>>>(p_h, W2, p_xw, 0);
    agg2_kernel<<<AGG2_BPG, 256>>>(p_xw, b2, out, 0);
    finalize_stats_kernel<<<1, 128>>>(0);
    norm_kernel<<<NB_NORM, 256>>>(out, 0);

    // ---- graph 1 pipeline on s3 ----
    cudaStreamWaitEvent(s3, ev_sout, 0);
    gemm_f32_kernel<<<GEMM_CTAS, 256, GEMM_F32_SMEM, s3>>>(feat2, W1, p_xw, N_NODES);
    cudaStreamWaitEvent(s3, ev_csr, 0);
    agg1_kernel<<<NB_AGG1, 256, 0, s3>>>(p_xw, b1, p_h, N_NODES);
    gemm_f16_kernel<<<GEMM_CTAS, 256, GEMM_F16_SMEM, s3>>>(p_h, W2, p_xw, N_NODES);
    agg2_kernel<<<AGG2_BPG, 256, 0, s3>>>(p_xw, b2, out, 1);
    finalize_stats_kernel<<<1, 128, 0, s3>>>(1);
    norm_kernel<<<NB_NORM, 256, 0, s3>>>(out, 1);
    cudaEventRecord(ev_g1, s3);

    // join so the captured graph's stream-0 tail covers both branches
    cudaStreamWaitEvent(0, ev_g1, 0);
}

// round 17
// speedup vs baseline: 1.2049x; 1.0821x over previous
#include <cuda_runtime.h>
#include <cuda_fp16.h>
#include <mma.h>
#include <math.h>
#include <stdint.h>

using namespace nvcuda;

#define N_NODES 100000
#define N_EDGES 800000
#define DIM 128
#define TWO_N (2 * N_NODES)
#define TWO_E (2 * N_EDGES)
#define NCHUNK ((TWO_N + 1023) / 1024)   // 196

// ---------------- scratch (no cudaMalloc allowed) ----------------
__device__ __half g_xw[TWO_N * DIM];     // GEMM output (fp16) / aggregation input
__device__ __half g_h [TWO_N * DIM];     // hidden layer (fp16, sout pre-folded)
__device__ int    g_deg_out[TWO_N];
__device__ int    g_deg_in [TWO_N];
__device__ float  g_sout[TWO_N];
__device__ float  g_sin [TWO_N];
__device__ int    g_rowptr[TWO_N + 1];
__device__ int    g_cursor[TWO_N];
__device__ int    g_cols[TWO_E];
__device__ int    g_partials[NCHUNK];
__device__ int    g_pprefix [NCHUNK];
__device__ double g_sum  [2 * DIM];
__device__ double g_sumsq[2 * DIM];
__device__ float  g_mean[2 * DIM];
__device__ float  g_istd[2 * DIM];

// ---------------- build kernels ----------------
__global__ void zero_kernel() {
    int i = blockIdx.x * blockDim.x + threadIdx.x;
    if (i < TWO_N) { g_deg_out[i] = 0; g_deg_in[i] = 0; }
    if (i < 2 * DIM) { g_sum[i] = 0.0; g_sumsq[i] = 0.0; }
}

// out-degrees only (critical path for gemm1)
__global__ void degree_out_kernel(const int* __restrict__ src1, const int* __restrict__ src2) {
    int i = blockIdx.x * blockDim.x + threadIdx.x;
    if (i < TWO_E) {
        int s;
        if (i < N_EDGES) s = src1[i];
        else             s = src2[i - N_EDGES] + N_NODES;
        atomicAdd(&g_deg_out[s], 1);
    }
}

__global__ void sout_kernel() {
    int i = blockIdx.x * blockDim.x + threadIdx.x;
    if (i < TWO_N) {
        int dout = g_deg_out[i]; if (dout < 1) dout = 1;
        g_sout[i] = rsqrtf((float)dout);
    }
}

// in-degrees only (CSR branch, overlapped with gemm1)
__global__ void degree_in_kernel(const int* __restrict__ dst1, const int* __restrict__ dst2) {
    int i = blockIdx.x * blockDim.x + threadIdx.x;
    if (i < TWO_E) {
        int d;
        if (i < N_EDGES) d = dst1[i];
        else             d = dst2[i - N_EDGES] + N_NODES;
        atomicAdd(&g_deg_in[d], 1);
    }
}

__device__ __forceinline__ int block_incl_scan256(int v) {
    int lane = threadIdx.x & 31, w = threadIdx.x >> 5;
    #pragma unroll
    for (int off = 1; off < 32; off <<= 1) {
        int t = __shfl_up_sync(0xffffffffu, v, off);
        if (lane >= off) v += t;
    }
    __shared__ int ws[8];
    if (lane == 31) ws[w] = v;
    __syncthreads();
    if (w == 0 && lane < 8) {
        int x = ws[lane];
        #pragma unroll
        for (int off = 1; off < 8; off <<= 1) {
            int t = __shfl_up_sync(0xffu, x, off);
            if (lane >= off) x += t;
        }
        ws[lane] = x;
    }
    __syncthreads();
    if (w > 0) v += ws[w - 1];
    return v;
}

// partial sums of deg_in + compute sin
__global__ void scan_partial_kernel() {
    int base = blockIdx.x * 1024 + threadIdx.x * 4;
    int s = 0;
    #pragma unroll
    for (int j = 0; j < 4; j++) {
        int i = base + j;
        if (i < TWO_N) {
            int din = g_deg_in[i];
            s += din;
            if (din < 1) din = 1;
            g_sin[i] = rsqrtf((float)din);
        }
    }
    __shared__ int red[256];
    red[threadIdx.x] = s; __syncthreads();
    #pragma unroll
    for (int off = 128; off > 0; off >>= 1) {
        if (threadIdx.x < off) red[threadIdx.x] += red[threadIdx.x + off];
        __syncthreads();
    }
    if (threadIdx.x == 0) g_partials[blockIdx.x] = red[0];
}

__global__ void scan_mid_kernel() {
    int t = threadIdx.x;
    int v = (t < NCHUNK) ? g_partials[t] : 0;
    int incl = block_incl_scan256(v);
    if (t < NCHUNK) g_pprefix[t] = incl - v;
    if (t == 0) g_rowptr[TWO_N] = TWO_E;
}

__global__ void scan_final_kernel() {
    int base = blockIdx.x * 1024 + threadIdx.x * 4;
    int d[4]; int s = 0;
    #pragma unroll
    for (int j = 0; j < 4; j++) { int i = base + j; d[j] = (i < TWO_N) ? g_deg_in[i] : 0; s += d[j]; }
    int incl = block_incl_scan256(s);
    int excl = incl - s + g_pprefix[blockIdx.x];
    #pragma unroll
    for (int j = 0; j < 4; j++) {
        int i = base + j;
        if (i < TWO_N) { g_rowptr[i] = excl; g_cursor[i] = excl; excl += d[j]; }
    }
}

__global__ void scatter_kernel(const int* __restrict__ src1, const int* __restrict__ dst1,
                               const int* __restrict__ src2, const int* __restrict__ dst2) {
    int i = blockIdx.x * blockDim.x + threadIdx.x;
    if (i < TWO_E) {
        int s, d;
        if (i < N_EDGES) { s = src1[i];                     d = dst1[i]; }
        else             { s = src2[i - N_EDGES] + N_NODES; d = dst2[i - N_EDGES] + N_NODES; }
        int p = atomicAdd(&g_cursor[d], 1);
        g_cols[p] = s;
    }
}

// ============ wmma GEMMs (per-graph: row range [row_base, row_base+N_NODES)) ============
#define LDH 136
#define G_NTILES ((N_NODES + 127) / 128)         // 782 tiles per graph
#define GEMM_CTAS 74                             // half-chip: two graphs co-reside

// --- layer 1: fp32 input, scale by sout, plain fp16 single-term MMA ---
#define F32_W   0
#define F32_A   (F32_W + 128 * LDH * 2)
#define F32_C   (F32_A + 128 * LDH * 2)          // fp32 C staging
#define GEMM_F32_SMEM (F32_C + 128 * 128 * 4)    // 135168

__global__ void __launch_bounds__(256, 1) gemm_f32_kernel(
    const float* __restrict__ X,       // this graph's features
    const float* __restrict__ W, __half* __restrict__ Yh,
    int row_base)
{
    extern __shared__ __align__(256) char smem[];
    __half* Ws  = (__half*)(smem + F32_W);
    __half* As  = (__half*)(smem + F32_A);
    float*  Cout = (float*)(smem + F32_C);

    int tid = threadIdx.x;
    int warp = tid >> 5;
    int lane = tid & 31;
    int row_end = row_base + N_NODES;

    for (int idx = tid; idx < DIM * DIM; idx += 256) {
        int k = idx >> 7, n = idx & 127;
        Ws[k * LDH + n] = __float2half_rn(W[idx]);
    }
    __syncthreads();

    int r  = tid >> 1;
    int kh = (tid & 1) * 64;

    for (int tile = blockIdx.x; tile < G_NTILES; tile += gridDim.x) {
        int row0 = row_base + tile * 128;
        __syncthreads();

        {
            int grow = row0 + r;
            if (grow < row_end) {
                const float* Xp = X + (size_t)(grow - row_base) * DIM;
                float s = g_sout[grow];
                #pragma unroll
                for (int j = 0; j < 16; j++) {
                    int c = kh + j * 4;
                    float4 xv = *(const float4*)&Xp[c];
                    __half2 p = __floats2half2_rn(xv.x * s, xv.y * s);
                    __half2 q = __floats2half2_rn(xv.z * s, xv.w * s);
                    uint2 u; u.x = *(uint32_t*)&p; u.y = *(uint32_t*)&q;
                    *(uint2*)&As[r * LDH + c] = u;
                }
            } else {
                #pragma unroll
                for (int j = 0; j < 16; j++) {
                    int c = kh + j * 4;
                    *(uint2*)&As[r * LDH + c] = make_uint2(0u, 0u);
                }
            }
        }
        __syncthreads();

        wmma::fragment<wmma::accumulator, 16, 16, 16, float> acc[8];
        #pragma unroll
        for (int n = 0; n < 8; n++) wmma::fill_fragment(acc[n], 0.0f);

        #pragma unroll
        for (int kk = 0; kk < 8; kk++) {
            wmma::fragment<wmma::matrix_a, 16, 16, 16, __half, wmma::row_major> a;
            wmma::load_matrix_sync(a, &As[(warp * 16) * LDH + kk * 16], LDH);
            #pragma unroll
            for (int n = 0; n < 8; n++) {
                wmma::fragment<wmma::matrix_b, 16, 16, 16, __half, wmma::row_major> b;
                wmma::load_matrix_sync(b, &Ws[(kk * 16) * LDH + n * 16], LDH);
                wmma::mma_sync(acc[n], a, b, acc[n]);
            }
        }

        #pragma unroll
        for (int n = 0; n < 8; n++)
            wmma::store_matrix_sync(&Cout[(warp * 16) * 128 + n * 16], acc[n], 128,
                                    wmma::mem_row_major);
        __syncwarp();

        #pragma unroll
        for (int rr = 0; rr < 16; rr++) {
            int grow = row0 + warp * 16 + rr;
            if (grow < row_end) {
                float4 v = *(float4*)&Cout[(warp * 16 + rr) * 128 + lane * 4];
                __half2 a = __floats2half2_rn(v.x, v.y);
                __half2 b = __floats2half2_rn(v.z, v.w);
                uint2 o; o.x = *(uint32_t*)&a; o.y = *(uint32_t*)&b;
                *(uint2*)&Yh[(size_t)grow * DIM + lane * 4] = o;
            }
        }
    }
}

// --- layer 2: fp16 input (sout pre-folded), plain fp16 single-term MMA ---
#define F16_W   0
#define F16_A   (F16_W + 128 * LDH * 2)
#define F16_C   (F16_A + 128 * LDH * 2)          // fp32 C staging
#define GEMM_F16_SMEM (F16_C + 128 * 128 * 4)    // 135168

__global__ void __launch_bounds__(256, 1) gemm_f16_kernel(
    const __half* __restrict__ Xh,     // global hidden buffer (full TWO_N rows)
    const float* __restrict__ W, __half* __restrict__ Yh,
    int row_base)
{
    extern __shared__ __align__(256) char smem[];
    __half* Ws  = (__half*)(smem + F16_W);
    __half* As  = (__half*)(smem + F16_A);
    float*  Cout = (float*)(smem + F16_C);

    int tid = threadIdx.x;
    int warp = tid >> 5;
    int lane = tid & 31;
    int row_end = row_base + N_NODES;

    for (int idx = tid; idx < DIM * DIM; idx += 256) {
        int k = idx >> 7, n = idx & 127;
        Ws[k * LDH + n] = __float2half_rn(W[idx]);
    }
    __syncthreads();

    int r  = tid >> 1;
    int kh = (tid & 1) * 64;

    for (int tile = blockIdx.x; tile < G_NTILES; tile += gridDim.x) {
        int row0 = row_base + tile * 128;
        __syncthreads();

        {
            int grow = row0 + r;
            if (grow < row_end) {
                const uint4* src = (const uint4*)&Xh[(size_t)grow * DIM + kh];
                uint4* dst = (uint4*)&As[r * LDH + kh];
                #pragma unroll
                for (int j = 0; j < 8; j++) dst[j] = src[j];
            } else {
                uint4* dst = (uint4*)&As[r * LDH + kh];
                #pragma unroll
                for (int j = 0; j < 8; j++) dst[j] = make_uint4(0u, 0u, 0u, 0u);
            }
        }
        __syncthreads();

        wmma::fragment<wmma::accumulator, 16, 16, 16, float> acc[8];
        #pragma unroll
        for (int n = 0; n < 8; n++) wmma::fill_fragment(acc[n], 0.0f);

        #pragma unroll
        for (int kk = 0; kk < 8; kk++) {
            wmma::fragment<wmma::matrix_a, 16, 16, 16, __half, wmma::row_major> a;
            wmma::load_matrix_sync(a, &As[(warp * 16) * LDH + kk * 16], LDH);
            #pragma unroll
            for (int n = 0; n < 8; n++) {
                wmma::fragment<wmma::matrix_b, 16, 16, 16, __half, wmma::row_major> b;
                wmma::load_matrix_sync(b, &Ws[(kk * 16) * LDH + n * 16], LDH);
                wmma::mma_sync(acc[n], a, b, acc[n]);
            }
        }

        #pragma unroll
        for (int n = 0; n < 8; n++)
            wmma::store_matrix_sync(&Cout[(warp * 16) * 128 + n * 16], acc[n], 128,
                                    wmma::mem_row_major);
        __syncwarp();

        #pragma unroll
        for (int rr = 0; rr < 16; rr++) {
            int grow = row0 + warp * 16 + rr;
            if (grow < row_end) {
                float4 v = *(float4*)&Cout[(warp * 16 + rr) * 128 + lane * 4];
                __half2 a = __floats2half2_rn(v.x, v.y);
                __half2 b = __floats2half2_rn(v.z, v.w);
                uint2 o; o.x = *(uint32_t*)&a; o.y = *(uint32_t*)&b;
                *(uint2*)&Yh[(size_t)grow * DIM + lane * 4] = o;
            }
        }
    }
}

// ---------------- shared agg body: fp16 gather, warp per node (MLP x2) ----------------
__device__ __forceinline__ float4 agg_gather(const __half* __restrict__ Xw,
                                             int node, int lane)
{
    int r0 = g_rowptr[node];
    int r1 = g_rowptr[node + 1];
    float4 a0 = make_float4(0.f, 0.f, 0.f, 0.f);
    float4 a1 = make_float4(0.f, 0.f, 0.f, 0.f);
    int e = r0;
    for (; e + 1 < r1; e += 2) {
        int c0 = g_cols[e], c1 = g_cols[e + 1];
        uint2 u0 = *(const uint2*)&Xw[(size_t)c0 * DIM + lane * 4];
        uint2 u1 = *(const uint2*)&Xw[(size_t)c1 * DIM + lane * 4];
        float2 p0 = __half22float2(*(__half2*)&u0.x);
        float2 q0 = __half22float2(*(__half2*)&u0.y);
        float2 p1 = __half22float2(*(__half2*)&u1.x);
        float2 q1 = __half22float2(*(__half2*)&u1.y);
        a0.x += p0.x; a0.y += p0.y; a0.z += q0.x; a0.w += q0.y;
        a1.x += p1.x; a1.y += p1.y; a1.z += q1.x; a1.w += q1.y;
    }
    if (e < r1) {
        int c0 = g_cols[e];
        uint2 u0 = *(const uint2*)&Xw[(size_t)c0 * DIM + lane * 4];
        float2 p0 = __half22float2(*(__half2*)&u0.x);
        float2 q0 = __half22float2(*(__half2*)&u0.y);
        a0.x += p0.x; a0.y += p0.y; a0.z += q0.x; a0.w += q0.y;
    }
    a0.x += a1.x; a0.y += a1.y; a0.z += a1.z; a0.w += a1.w;
    return a0;
}

// agg1 (per graph): h' = relu(agg*sin + b) * sout, fp16 out; one node per warp
__global__ void agg1_kernel(const __half* __restrict__ Xw,
                            const float* __restrict__ bias,
                            __half* __restrict__ outh, int node_base)
{
    int n = (blockIdx.x * blockDim.x + threadIdx.x) >> 5;
    int lane = threadIdx.x & 31;
    if (n >= N_NODES) return;
    int node = node_base + n;
    float4 a = agg_gather(Xw, node, lane);
    float s = g_sin[node];
    float so = g_sout[node];
    float4 b = *(const float4*)&bias[lane * 4];
    float4 o;
    o.x = fmaxf(a.x * s + b.x, 0.f) * so;
    o.y = fmaxf(a.y * s + b.y, 0.f) * so;
    o.z = fmaxf(a.z * s + b.z, 0.f) * so;
    o.w = fmaxf(a.w * s + b.w, 0.f) * so;
    __half2 p = __floats2half2_rn(o.x, o.y);
    __half2 q = __floats2half2_rn(o.z, o.w);
    uint2 u; u.x = *(uint32_t*)&p; u.y = *(uint32_t*)&q;
    *(uint2*)&outh[(size_t)node * DIM + lane * 4] = u;
}

// agg2 (per graph): out = agg*sin + b (fp32), fused register column stats
#define AGG2_BPG 296

__global__ void __launch_bounds__(256) agg2_kernel(const __half* __restrict__ Xw,
                            const float* __restrict__ bias,
                            float* __restrict__ out, int graph)
{
    __shared__ float ssum[8][128];
    __shared__ float ssq [8][128];

    int tid = threadIdx.x;
    int wip = tid >> 5;
    int lane = tid & 31;
    int wg = blockIdx.x * 8 + wip;
    const int WSTRIDE = AGG2_BPG * 8;
    int nbase = graph * N_NODES;

    float4 b = *(const float4*)&bias[lane * 4];
    float4 rsum = make_float4(0.f, 0.f, 0.f, 0.f);
    float4 rsq  = make_float4(0.f, 0.f, 0.f, 0.f);

    for (int n = wg; n < N_NODES; n += WSTRIDE) {
        int node = nbase + n;
        float4 a = agg_gather(Xw, node, lane);
        float s = g_sin[node];
        float4 o;
        o.x = a.x * s + b.x; o.y = a.y * s + b.y;
        o.z = a.z * s + b.z; o.w = a.w * s + b.w;
        *(float4*)&out[(size_t)node * DIM + lane * 4] = o;
        rsum.x += o.x; rsum.y += o.y; rsum.z += o.z; rsum.w += o.w;
        rsq.x += o.x * o.x; rsq.y += o.y * o.y;
        rsq.z += o.z * o.z; rsq.w += o.w * o.w;
    }

    *(float4*)&ssum[wip][lane * 4] = rsum;
    *(float4*)&ssq [wip][lane * 4] = rsq;
    __syncthreads();

    if (tid < 128) {
        float ts = 0.f, tq = 0.f;
        #pragma unroll
        for (int w = 0; w < 8; w++) { ts += ssum[w][tid]; tq += ssq[w][tid]; }
        atomicAdd(&g_sum  [graph * DIM + tid], (double)ts);
        atomicAdd(&g_sumsq[graph * DIM + tid], (double)tq);
    }
}

// ---------------- per-graph stats finalize + z-score ----------------
__global__ void finalize_stats_kernel(int graph) {
    int c = threadIdx.x;
    if (c < DIM) {
        int m = graph * DIM + c;
        double mean = g_sum[m] / (double)N_NODES;
        double var  = (g_sumsq[m] - mean * mean * (double)N_NODES) / (double)(N_NODES - 1);
        g_mean[m] = (float)mean;
        g_istd[m] = (float)(1.0 / sqrt(var));
    }
}

__global__ void norm_kernel(float* __restrict__ h, int graph) {
    int i = blockIdx.x * blockDim.x + threadIdx.x;
    const int total = N_NODES * DIM / 4;
    if (i < total) {
        float4* p = (float4*)h + (size_t)graph * total + i;
        float4 v = *p;
        int c = (i * 4) & 127;
        int m = graph * DIM + c;
        v.x = (v.x - g_mean[m + 0]) * g_istd[m + 0];
        v.y = (v.y - g_mean[m + 1]) * g_istd[m + 1];
        v.z = (v.z - g_mean[m + 2]) * g_istd[m + 2];
        v.w = (v.w - g_mean[m + 3]) * g_istd[m + 3];
        *p = v;
    }
}

// ---------------- launch ----------------
extern "C" void kernel_launch(void* const* d_in, const int* in_sizes, int n_in,
                              void* d_out, int out_size)
{
    const float* feat1 = (const float*)d_in[0];
    const float* feat2 = (const float*)d_in[1];
    const float* W1    = (const float*)d_in[2];
    const float* b1    = (const float*)d_in[3];
    const float* W2    = (const float*)d_in[4];
    const float* b2    = (const float*)d_in[5];
    const int*   src1  = (const int*)d_in[6];
    const int*   dst1  = (const int*)d_in[7];
    const int*   src2  = (const int*)d_in[8];
    const int*   dst2  = (const int*)d_in[9];
    float* out = (float*)d_out;

    static cudaStream_t s2 = nullptr, s3 = nullptr;
    static cudaEvent_t ev_zero = nullptr, ev_sout = nullptr,
                       ev_csr = nullptr, ev_g1 = nullptr;
    if (!s2) {
        cudaStreamCreateWithFlags(&s2, cudaStreamNonBlocking);
        cudaStreamCreateWithFlags(&s3, cudaStreamNonBlocking);
        cudaEventCreateWithFlags(&ev_zero, cudaEventDisableTiming);
        cudaEventCreateWithFlags(&ev_sout, cudaEventDisableTiming);
        cudaEventCreateWithFlags(&ev_csr,  cudaEventDisableTiming);
        cudaEventCreateWithFlags(&ev_g1,   cudaEventDisableTiming);
        cudaFuncSetAttribute(gemm_f32_kernel,
                             cudaFuncAttributeMaxDynamicSharedMemorySize, GEMM_F32_SMEM);
        cudaFuncSetAttribute(gemm_f16_kernel,
                             cudaFuncAttributeMaxDynamicSharedMemorySize, GEMM_F16_SMEM);
    }

    __half* p_xw = nullptr; __half* p_h = nullptr;
    cudaGetSymbolAddress((void**)&p_xw, g_xw);
    cudaGetSymbolAddress((void**)&p_h,  g_h);

    const int NB_2N  = (TWO_N + 255) / 256;
    const int NB_2E  = (TWO_E + 255) / 256;
    const int NB_AGG1 = (N_NODES * 32 + 255) / 256;      // 12500 blocks per graph
    const int NB_NORM = (N_NODES * DIM / 4 + 255) / 256; // per graph

    // ---- stream 0: minimal critical path to GEMM-1 ----
    zero_kernel<<<NB_2N, 256>>>();
    cudaEventRecord(ev_zero, 0);
    degree_out_kernel<<<NB_2E, 256>>>(src1, src2);
    sout_kernel<<<NB_2N, 256>>>();
    cudaEventRecord(ev_sout, 0);

    // ---- s2: in-degree + CSR chain (hidden under GEMM-1) ----
    cudaStreamWaitEvent(s2, ev_zero, 0);
    degree_in_kernel<<<NB_2E, 256, 0, s2>>>(dst1, dst2);
    scan_partial_kernel<<<NCHUNK, 256, 0, s2>>>();   // sin + partials
    scan_mid_kernel<<<1, 256, 0, s2>>>();
    scan_final_kernel<<<NCHUNK, 256, 0, s2>>>();
    scatter_kernel<<<NB_2E, 256, 0, s2>>>(src1, dst1, src2, dst2);
    cudaEventRecord(ev_csr, s2);

    // ---- graph 0 pipeline on stream 0 ----
    gemm_f32_kernel<<<GEMM_CTAS, 256, GEMM_F32_SMEM>>>(feat1, W1, p_xw, 0);
    cudaStreamWaitEvent(0, ev_csr, 0);
    agg1_kernel<<<NB_AGG1, 256>>>(p_xw, b1, p_h, 0);
    gemm_f16_kernel<<<GEMM_CTAS, 256, GEMM_F16_SMEM>>>(p_h, W2, p_xw, 0);
    agg2_kernel<<<AGG2_BPG, 256>>>(p_xw, b2, out, 0);
    finalize_stats_kernel<<<1, 128>>>(0);
    norm_kernel<<<NB_NORM, 256>>>(out, 0);

    // ---- graph 1 pipeline on s3 ----
    cudaStreamWaitEvent(s3, ev_sout, 0);
    gemm_f32_kernel<<<GEMM_CTAS, 256, GEMM_F32_SMEM, s3>>>(feat2, W1, p_xw, N_NODES);
    cudaStreamWaitEvent(s3, ev_csr, 0);
    agg1_kernel<<<NB_AGG1, 256, 0, s3>>>(p_xw, b1, p_h, N_NODES);
    gemm_f16_kernel<<<GEMM_CTAS, 256, GEMM_F16_SMEM, s3>>>(p_h, W2, p_xw, N_NODES);
    agg2_kernel<<<AGG2_BPG, 256, 0, s3>>>(p_xw, b2, out, 1);
    finalize_stats_kernel<<<1, 128, 0, s3>>>(1);
    norm_kernel<<<NB_NORM, 256, 0, s3>>>(out, 1);
    cudaEventRecord(ev_g1, s3);

    // join so the captured graph's stream-0 tail covers both branches
    cudaStreamWaitEvent(0, ev_g1, 0);
}